// round 1
// baseline (speedup 1.0000x reference)
#include <cuda_runtime.h>
#include <math.h>
#include <stdint.h>

// Problem dims (fixed for this dataset entry)
#define NT 8192   // tokens = B*S
#define NH 1024   // hidden
#define NE 8      // experts
#define NI 1408   // intermediate

// ---------------- scratch (device globals; no allocation allowed) ----------
__device__ float g_hbuf[(size_t)NE * NT * NI];   // expert SwiGLU activations, row = e*NT + local_row
__device__ float g_shh [(size_t)NT * NI];        // shared-expert SwiGLU activations
__device__ float g_down[(size_t)2  * NT * NH];   // per-(token,k) expert down outputs, row = 2*t + k
__device__ int   g_rowlist[NE * NT];             // token id per (expert, local row)
__device__ int   g_pidlist[NE * NT];             // pair id (2t+k) per (expert, local row)
__device__ int   g_cnt[NE];
__device__ float g_w[NT * 2];                    // renormalized top-2 weights

// ---------------- counters reset -------------------------------------------
__global__ void zero_cnt_kernel() {
    if (threadIdx.x < NE) g_cnt[threadIdx.x] = 0;
}

// ---------------- router: logits -> softmax -> top2 -> scatter -------------
__global__ void router_kernel(const float* __restrict__ x,
                              const float* __restrict__ gw) {
    int gtid = blockIdx.x * blockDim.x + threadIdx.x;
    int t    = gtid >> 5;
    int lane = gtid & 31;
    if (t >= NT) return;
    const float* xr = x + (size_t)t * NH;

    float acc[8] = {0.f,0.f,0.f,0.f,0.f,0.f,0.f,0.f};
    for (int h = lane; h < NH; h += 32) {
        float xv = __ldg(xr + h);
        const float4* g4 = reinterpret_cast<const float4*>(gw + (size_t)h * 8);
        float4 a = __ldg(g4 + 0);
        float4 b = __ldg(g4 + 1);
        acc[0] = fmaf(xv, a.x, acc[0]);
        acc[1] = fmaf(xv, a.y, acc[1]);
        acc[2] = fmaf(xv, a.z, acc[2]);
        acc[3] = fmaf(xv, a.w, acc[3]);
        acc[4] = fmaf(xv, b.x, acc[4]);
        acc[5] = fmaf(xv, b.y, acc[5]);
        acc[6] = fmaf(xv, b.z, acc[6]);
        acc[7] = fmaf(xv, b.w, acc[7]);
    }
    #pragma unroll
    for (int e = 0; e < 8; e++) {
        #pragma unroll
        for (int off = 16; off > 0; off >>= 1)
            acc[e] += __shfl_xor_sync(0xffffffffu, acc[e], off);
    }
    if (lane == 0) {
        float m = acc[0];
        #pragma unroll
        for (int e = 1; e < 8; e++) m = fmaxf(m, acc[e]);
        float p[8], s = 0.f;
        #pragma unroll
        for (int e = 0; e < 8; e++) { p[e] = expf(acc[e] - m); s += p[e]; }
        float inv = 1.f / s;
        #pragma unroll
        for (int e = 0; e < 8; e++) p[e] *= inv;

        int i0 = 0; float v0 = p[0];
        #pragma unroll
        for (int e = 1; e < 8; e++) if (p[e] > v0) { v0 = p[e]; i0 = e; }
        int i1 = -1; float v1 = -1.f;
        #pragma unroll
        for (int e = 0; e < 8; e++) if (e != i0 && p[e] > v1) { v1 = p[e]; i1 = e; }

        float denom = v0 + v1 + 1e-6f;
        g_w[2*t]   = v0 / denom;
        g_w[2*t+1] = v1 / denom;

        int r0 = atomicAdd(&g_cnt[i0], 1);
        g_rowlist[i0*NT + r0] = t;
        g_pidlist[i0*NT + r0] = 2*t;
        int r1 = atomicAdd(&g_cnt[i1], 1);
        g_rowlist[i1*NT + r1] = t;
        g_pidlist[i1*NT + r1] = 2*t + 1;
    }
}

// ---------------- fused gate+up SwiGLU GEMM --------------------------------
// C[r, n] = silu(X[r,:] @ Wg[:,n]) * (X[r,:] @ Wu[:,n])
// Tile: 128(M) x 64(N) x 8(K), 256 threads, per-thread 8x4 (x2 accumulators)
template<bool EXPERT>
__global__ __launch_bounds__(256)
void gateup_kernel(const float* __restrict__ X,
                   const float* __restrict__ Wg,
                   const float* __restrict__ Wu) {
    __shared__ float As [8][128];
    __shared__ float sBg[8][64];
    __shared__ float sBu[8][64];

    const int e    = EXPERT ? blockIdx.z : 0;
    const int M    = EXPERT ? g_cnt[e] : NT;
    const int row0 = blockIdx.y * 128;
    if (row0 >= M) return;
    const int col0 = blockIdx.x * 64;

    const float* wg = Wg + (EXPERT ? (size_t)e * NH * NI : (size_t)0);
    const float* wu = Wu + (EXPERT ? (size_t)e * NH * NI : (size_t)0);
    float* Hout = EXPERT ? (g_hbuf + (size_t)e * NT * NI) : g_shh;

    const int tid  = threadIdx.x;
    const int arow = tid >> 1;
    const int akc  = (tid & 1) * 4;
    const bool avalid = (row0 + arow) < M;
    int grow;
    if (EXPERT) grow = avalid ? g_rowlist[e*NT + row0 + arow] : 0;
    else        grow = row0 + arow;
    const float* aptr = X + (size_t)grow * NH + akc;

    const int bsel = tid >> 7;                 // 0 -> gate, 1 -> up
    const int bt   = tid & 127;
    const int bk   = bt >> 4;
    const int bc   = (bt & 15) * 4;
    const float* bptr = (bsel ? wu : wg) + (size_t)bk * NI + col0 + bc;

    const int ty = tid >> 4;
    const int tx = tid & 15;

    float accg[8][4], accu[8][4];
    #pragma unroll
    for (int i = 0; i < 8; i++)
        #pragma unroll
        for (int j = 0; j < 4; j++) { accg[i][j] = 0.f; accu[i][j] = 0.f; }

    for (int k0 = 0; k0 < NH; k0 += 8) {
        float4 av = make_float4(0.f,0.f,0.f,0.f);
        if (avalid) av = *reinterpret_cast<const float4*>(aptr + k0);
        float4 bv = *reinterpret_cast<const float4*>(bptr + (size_t)k0 * NI);
        __syncthreads();
        As[akc+0][arow] = av.x;
        As[akc+1][arow] = av.y;
        As[akc+2][arow] = av.z;
        As[akc+3][arow] = av.w;
        if (bsel == 0) *reinterpret_cast<float4*>(&sBg[bk][bc]) = bv;
        else           *reinterpret_cast<float4*>(&sBu[bk][bc]) = bv;
        __syncthreads();
        #pragma unroll
        for (int kk = 0; kk < 8; kk++) {
            float a[8], bg[4], bu[4];
            #pragma unroll
            for (int i = 0; i < 8; i++) a[i] = As[kk][ty*8+i];
            #pragma unroll
            for (int j = 0; j < 4; j++) { bg[j] = sBg[kk][tx*4+j]; bu[j] = sBu[kk][tx*4+j]; }
            #pragma unroll
            for (int i = 0; i < 8; i++)
                #pragma unroll
                for (int j = 0; j < 4; j++) {
                    accg[i][j] = fmaf(a[i], bg[j], accg[i][j]);
                    accu[i][j] = fmaf(a[i], bu[j], accu[i][j]);
                }
        }
    }

    #pragma unroll
    for (int i = 0; i < 8; i++) {
        int r = row0 + ty*8 + i;
        if (r < M) {
            float g0 = accg[i][0], g1 = accg[i][1], g2 = accg[i][2], g3 = accg[i][3];
            float4 hv;
            hv.x = g0 / (1.f + expf(-g0)) * accu[i][0];
            hv.y = g1 / (1.f + expf(-g1)) * accu[i][1];
            hv.z = g2 / (1.f + expf(-g2)) * accu[i][2];
            hv.w = g3 / (1.f + expf(-g3)) * accu[i][3];
            *reinterpret_cast<float4*>(Hout + (size_t)r * NI + col0 + tx*4) = hv;
        }
    }
}

// ---------------- down GEMM -------------------------------------------------
// C[r, n] = H[r,:] @ Wd[:,n];  expert rows scatter to per-pair buffer.
// Tile: 128 x 128 x 8, 256 threads, per-thread 8x8
template<bool EXPERT>
__global__ __launch_bounds__(256)
void down_kernel(const float* __restrict__ Wd, float* __restrict__ outp) {
    __shared__ float As[8][128];
    __shared__ float Bs[8][128];

    const int e    = EXPERT ? blockIdx.z : 0;
    const int M    = EXPERT ? g_cnt[e] : NT;
    const int row0 = blockIdx.y * 128;
    if (row0 >= M) return;
    const int col0 = blockIdx.x * 128;

    const float* A = EXPERT ? (g_hbuf + (size_t)e * NT * NI) : g_shh;
    const float* B = Wd + (EXPERT ? (size_t)e * NI * NH : (size_t)0);

    const int tid  = threadIdx.x;
    const int arow = tid >> 1;
    const int akc  = (tid & 1) * 4;
    const bool avalid = (row0 + arow) < M;
    const float* aptr = A + (size_t)(row0 + arow) * NI + akc;
    const int bk = tid >> 5;
    const int bc = (tid & 31) * 4;
    const float* bptr = B + (size_t)bk * NH + col0 + bc;

    const int ty = tid >> 4, tx = tid & 15;
    float acc[8][8];
    #pragma unroll
    for (int i = 0; i < 8; i++)
        #pragma unroll
        for (int j = 0; j < 8; j++) acc[i][j] = 0.f;

    for (int k0 = 0; k0 < NI; k0 += 8) {
        float4 av = make_float4(0.f,0.f,0.f,0.f);
        if (avalid) av = *reinterpret_cast<const float4*>(aptr + k0);
        float4 bv = *reinterpret_cast<const float4*>(bptr + (size_t)k0 * NH);
        __syncthreads();
        As[akc+0][arow] = av.x;
        As[akc+1][arow] = av.y;
        As[akc+2][arow] = av.z;
        As[akc+3][arow] = av.w;
        *reinterpret_cast<float4*>(&Bs[bk][bc]) = bv;
        __syncthreads();
        #pragma unroll
        for (int kk = 0; kk < 8; kk++) {
            float a[8], b[8];
            #pragma unroll
            for (int i = 0; i < 8; i++) a[i] = As[kk][ty*8+i];
            #pragma unroll
            for (int j = 0; j < 8; j++) b[j] = Bs[kk][tx*8+j];
            #pragma unroll
            for (int i = 0; i < 8; i++)
                #pragma unroll
                for (int j = 0; j < 8; j++)
                    acc[i][j] = fmaf(a[i], b[j], acc[i][j]);
        }
    }

    #pragma unroll
    for (int i = 0; i < 8; i++) {
        int r = row0 + ty*8 + i;
        if (r < M) {
            float* crow;
            if (EXPERT) crow = g_down + (size_t)g_pidlist[e*NT + r] * NH;
            else        crow = outp   + (size_t)r * NH;
            float4 c0 = make_float4(acc[i][0],acc[i][1],acc[i][2],acc[i][3]);
            float4 c1 = make_float4(acc[i][4],acc[i][5],acc[i][6],acc[i][7]);
            *reinterpret_cast<float4*>(crow + col0 + tx*8)     = c0;
            *reinterpret_cast<float4*>(crow + col0 + tx*8 + 4) = c1;
        }
    }
}

// ---------------- combine: out = shared + w0*d0 + w1*d1 --------------------
__global__ void combine_kernel(float* __restrict__ outp) {
    int t = blockIdx.x;
    int i = threadIdx.x;              // 256 threads * float4 = 1024 floats
    float w0 = g_w[2*t], w1 = g_w[2*t+1];
    float4*       o = reinterpret_cast<float4*>(outp + (size_t)t * NH);
    const float4* a = reinterpret_cast<const float4*>(g_down + (size_t)(2*t)   * NH);
    const float4* b = reinterpret_cast<const float4*>(g_down + (size_t)(2*t+1) * NH);
    float4 ov = o[i], av = a[i], bv = b[i];
    ov.x = fmaf(w1, bv.x, fmaf(w0, av.x, ov.x));
    ov.y = fmaf(w1, bv.y, fmaf(w0, av.y, ov.y));
    ov.z = fmaf(w1, bv.z, fmaf(w0, av.z, ov.z));
    ov.w = fmaf(w1, bv.w, fmaf(w0, av.w, ov.w));
    o[i] = ov;
}

// ---------------- launch ----------------------------------------------------
extern "C" void kernel_launch(void* const* d_in, const int* in_sizes, int n_in,
                              void* d_out, int out_size) {
    const float* x  = (const float*)d_in[0];
    const float* gw = (const float*)d_in[1];
    const float* eg = (const float*)d_in[2];
    const float* eu = (const float*)d_in[3];
    const float* ed = (const float*)d_in[4];
    const float* sg = (const float*)d_in[5];
    const float* su = (const float*)d_in[6];
    const float* sd = (const float*)d_in[7];
    float* out = (float*)d_out;

    zero_cnt_kernel<<<1, 32>>>();
    router_kernel<<<NT/4, 128>>>(x, gw);                       // 4 warps/block

    dim3 gshared_gu(NI/64, NT/128, 1);                         // (22, 64)
    gateup_kernel<false><<<gshared_gu, 256>>>(x, sg, su);
    dim3 gexp_gu(NI/64, NT/128, NE);                           // (22, 64, 8) early-exit on cnt
    gateup_kernel<true><<<gexp_gu, 256>>>(x, eg, eu);

    dim3 gshared_dn(NH/128, NT/128, 1);                        // (8, 64)
    down_kernel<false><<<gshared_dn, 256>>>(sd, out);
    dim3 gexp_dn(NH/128, NT/128, NE);                          // (8, 64, 8)
    down_kernel<true><<<gexp_dn, 256>>>(ed, out);

    combine_kernel<<<NT, 256>>>(out);
}

// round 3
// speedup vs baseline: 1.8907x; 1.8907x over previous
#include <cuda_runtime.h>
#include <math.h>
#include <stdint.h>

// Problem dims (fixed)
#define NT 8192   // tokens
#define NH 1024   // hidden
#define NE 8      // experts
#define NI 1408   // intermediate

#define KC 32     // K per pipeline stage

// gateup stage layout (floats): A[128][36] + Bg[32][72] + Bu[32][72]
#define GU_A_PAD 36
#define GU_B_PAD 72
#define GU_A_FLOATS (128 * GU_A_PAD)                  // 4608
#define GU_BG_OFF   GU_A_FLOATS
#define GU_BU_OFF   (GU_A_FLOATS + 32 * GU_B_PAD)
#define GU_STAGE_FLOATS (GU_A_FLOATS + 2 * 32 * GU_B_PAD)   // 9216
#define GU_SMEM_BYTES (3 * GU_STAGE_FLOATS * 4)             // 110592

// down stage layout: A[128][36] + B[32][136]
#define DN_A_PAD 36
#define DN_B_PAD 136
#define DN_A_FLOATS (128 * DN_A_PAD)
#define DN_B_OFF    DN_A_FLOATS
#define DN_STAGE_FLOATS (DN_A_FLOATS + 32 * DN_B_PAD)       // 8960
#define DN_SMEM_BYTES (3 * DN_STAGE_FLOATS * 4)             // 107520

// ---------------- scratch (device globals) ----------------------------------
__device__ float g_hbuf[(size_t)NE * NT * NI];   // expert SwiGLU activations (local rows)
__device__ float g_shh [(size_t)NT * NI];        // shared SwiGLU activations
__device__ float g_down[(size_t)2  * NT * NH];   // per-(token,k) down outputs
__device__ int   g_rowlist[NE * NT];             // token id per (expert, local row)
__device__ int   g_pidlist[NE * NT];             // pair id (2t+k)
__device__ int   g_cnt[NE];
__device__ float g_w[NT * 2];

// ---------------- helpers ----------------------------------------------------
__device__ __forceinline__ uint32_t smem_u32(const void* p) {
    uint32_t a;
    asm("{ .reg .u64 t; cvta.to.shared.u64 t, %1; cvt.u32.u64 %0, t; }" : "=r"(a) : "l"(p));
    return a;
}
__device__ __forceinline__ void cpa16(uint32_t dst, const float* src) {
    asm volatile("cp.async.cg.shared.global [%0], [%1], 16;" :: "r"(dst), "l"(src) : "memory");
}
__device__ __forceinline__ void cp_commit() {
    asm volatile("cp.async.commit_group;" ::: "memory");
}
// load fp32 from smem and round-to-nearest tf32 (bits kept in b32 reg)
__device__ __forceinline__ uint32_t ldrna(const float* p) {
    uint32_t r;
    asm("cvt.rna.tf32.f32 %0, %1;" : "=r"(r) : "f"(*p));
    return r;
}
__device__ __forceinline__ void mma_tf32(float* c, const uint32_t* a, const uint32_t* b) {
    asm volatile(
        "mma.sync.aligned.m16n8k8.row.col.f32.tf32.tf32.f32 "
        "{%0,%1,%2,%3}, {%4,%5,%6,%7}, {%8,%9}, {%0,%1,%2,%3};"
        : "+f"(c[0]), "+f"(c[1]), "+f"(c[2]), "+f"(c[3])
        : "r"(a[0]), "r"(a[1]), "r"(a[2]), "r"(a[3]), "r"(b[0]), "r"(b[1]));
}

// ---------------- small kernels ----------------------------------------------
__global__ void zero_cnt_kernel() {
    if (threadIdx.x < NE) g_cnt[threadIdx.x] = 0;
}

// ---------------- router ------------------------------------------------------
__global__ void router_kernel(const float* __restrict__ x,
                              const float* __restrict__ gw) {
    int gtid = blockIdx.x * blockDim.x + threadIdx.x;
    int t    = gtid >> 5;
    int lane = gtid & 31;
    if (t >= NT) return;
    const float* xr = x + (size_t)t * NH;

    float acc[8] = {0.f,0.f,0.f,0.f,0.f,0.f,0.f,0.f};
    for (int h = lane; h < NH; h += 32) {
        float xv = __ldg(xr + h);
        const float4* g4 = reinterpret_cast<const float4*>(gw + (size_t)h * 8);
        float4 a = __ldg(g4 + 0);
        float4 b = __ldg(g4 + 1);
        acc[0] = fmaf(xv, a.x, acc[0]); acc[1] = fmaf(xv, a.y, acc[1]);
        acc[2] = fmaf(xv, a.z, acc[2]); acc[3] = fmaf(xv, a.w, acc[3]);
        acc[4] = fmaf(xv, b.x, acc[4]); acc[5] = fmaf(xv, b.y, acc[5]);
        acc[6] = fmaf(xv, b.z, acc[6]); acc[7] = fmaf(xv, b.w, acc[7]);
    }
    #pragma unroll
    for (int e = 0; e < 8; e++)
        #pragma unroll
        for (int off = 16; off > 0; off >>= 1)
            acc[e] += __shfl_xor_sync(0xffffffffu, acc[e], off);
    if (lane == 0) {
        float m = acc[0];
        #pragma unroll
        for (int e = 1; e < 8; e++) m = fmaxf(m, acc[e]);
        float p[8], s = 0.f;
        #pragma unroll
        for (int e = 0; e < 8; e++) { p[e] = expf(acc[e] - m); s += p[e]; }
        float inv = 1.f / s;
        #pragma unroll
        for (int e = 0; e < 8; e++) p[e] *= inv;
        int i0 = 0; float v0 = p[0];
        #pragma unroll
        for (int e = 1; e < 8; e++) if (p[e] > v0) { v0 = p[e]; i0 = e; }
        int i1 = -1; float v1 = -1.f;
        #pragma unroll
        for (int e = 0; e < 8; e++) if (e != i0 && p[e] > v1) { v1 = p[e]; i1 = e; }
        float denom = v0 + v1 + 1e-6f;
        g_w[2*t]   = v0 / denom;
        g_w[2*t+1] = v1 / denom;
        int r0 = atomicAdd(&g_cnt[i0], 1);
        g_rowlist[i0*NT + r0] = t; g_pidlist[i0*NT + r0] = 2*t;
        int r1 = atomicAdd(&g_cnt[i1], 1);
        g_rowlist[i1*NT + r1] = t; g_pidlist[i1*NT + r1] = 2*t + 1;
    }
}

// ---------------- gate+up SwiGLU GEMM (mma.sync tf32) -------------------------
// Block: M=128 tokens x N=64 cols (for BOTH gate and up). 256 threads, 8 warps.
// Warp tile: 32(M) x 32(N) per matrix. H[lrow, col] = silu(g)*u.
template<bool EXPERT>
__global__ __launch_bounds__(256)
void gateup_mma(const float* __restrict__ X,
                const float* __restrict__ Wg,   // [*, NH, NI] n-contiguous
                const float* __restrict__ Wu) {
    extern __shared__ float smem[];
    const int e    = EXPERT ? blockIdx.z : 0;
    const int M    = EXPERT ? g_cnt[e] : NT;
    const int row0 = blockIdx.y * 128;
    if (row0 >= M) return;
    const int col0 = blockIdx.x * 64;

    const float* wg = Wg + (EXPERT ? (size_t)e * NH * NI : (size_t)0);
    const float* wu = Wu + (EXPERT ? (size_t)e * NH * NI : (size_t)0);
    float* Hout = EXPERT ? (g_hbuf + (size_t)e * NT * NI) : g_shh;

    const int tid  = threadIdx.x, wid = tid >> 5, lane = tid & 31;
    const uint32_t sbase = smem_u32(smem);

    // --- per-thread cp.async role -------------------------------------------
    const float* src;     // advances by sstep per stage
    size_t sstep;
    int dst_off;          // float offset within stage
    if (tid < 128) {
        int r = tid;
        int li = row0 + r; if (li >= M) li = M - 1;
        int gr = EXPERT ? g_rowlist[e*NT + li] : li;
        src = X + (size_t)gr * NH;
        sstep = KC;
        dst_off = r * GU_A_PAD;
    } else if (tid < 192) {
        int u = tid - 128, r = u >> 1, half = u & 1;
        src = wg + (size_t)r * NI + col0 + half * 32;
        sstep = (size_t)KC * NI;
        dst_off = GU_BG_OFF + r * GU_B_PAD + half * 32;
    } else {
        int u = tid - 192, r = u >> 1, half = u & 1;
        src = wu + (size_t)r * NI + col0 + half * 32;
        sstep = (size_t)KC * NI;
        dst_off = GU_BU_OFF + r * GU_B_PAD + half * 32;
    }

    float accg[2][4][4], accu[2][4][4];
    #pragma unroll
    for (int i = 0; i < 2; i++)
        #pragma unroll
        for (int j = 0; j < 4; j++)
            #pragma unroll
            for (int q = 0; q < 4; q++) { accg[i][j][q] = 0.f; accu[i][j][q] = 0.f; }

    const int m0 = (wid & 3) * 32, n0 = (wid >> 2) * 32;
    const int tg = lane >> 2, ti = lane & 3;

    // prologue: stages 0, 1
    #pragma unroll
    for (int s = 0; s < 2; s++) {
        uint32_t d = sbase + (uint32_t)(s * GU_STAGE_FLOATS + dst_off) * 4;
        #pragma unroll
        for (int c = 0; c < 8; c++) cpa16(d + c*16, src + c*4);
        cp_commit();
        src += sstep;
    }

    const int KST = NH / KC;   // 32
    for (int j = 0; j < KST; j++) {
        if (j < KST - 1) asm volatile("cp.async.wait_group 1;" ::: "memory");
        else             asm volatile("cp.async.wait_group 0;" ::: "memory");
        __syncthreads();
        if (j + 2 < KST) {
            int s = (j + 2) % 3;
            uint32_t d = sbase + (uint32_t)(s * GU_STAGE_FLOATS + dst_off) * 4;
            #pragma unroll
            for (int c = 0; c < 8; c++) cpa16(d + c*16, src + c*4);
            cp_commit();
            src += sstep;
        }
        const float* sA  = smem + (j % 3) * GU_STAGE_FLOATS;
        const float* sBg = sA + GU_BG_OFF;
        const float* sBu = sA + GU_BU_OFF;
        #pragma unroll
        for (int kk = 0; kk < 4; kk++) {
            const int k0 = kk * 8;
            uint32_t a[2][4];
            #pragma unroll
            for (int i = 0; i < 2; i++) {
                int r = m0 + i*16 + tg;
                a[i][0] = ldrna(sA + (size_t)r     * GU_A_PAD + k0 + ti);
                a[i][1] = ldrna(sA + (size_t)(r+8) * GU_A_PAD + k0 + ti);
                a[i][2] = ldrna(sA + (size_t)r     * GU_A_PAD + k0 + 4 + ti);
                a[i][3] = ldrna(sA + (size_t)(r+8) * GU_A_PAD + k0 + 4 + ti);
            }
            #pragma unroll
            for (int jn = 0; jn < 4; jn++) {
                int n = n0 + jn*8 + tg;
                uint32_t bg[2], bu[2];
                bg[0] = ldrna(sBg + (size_t)(k0 + ti)     * GU_B_PAD + n);
                bg[1] = ldrna(sBg + (size_t)(k0 + 4 + ti) * GU_B_PAD + n);
                bu[0] = ldrna(sBu + (size_t)(k0 + ti)     * GU_B_PAD + n);
                bu[1] = ldrna(sBu + (size_t)(k0 + 4 + ti) * GU_B_PAD + n);
                #pragma unroll
                for (int i = 0; i < 2; i++) {
                    mma_tf32(accg[i][jn], a[i], bg);
                    mma_tf32(accu[i][jn], a[i], bu);
                }
            }
        }
    }

    // epilogue: silu(g)*u, write rows
    #pragma unroll
    for (int i = 0; i < 2; i++) {
        #pragma unroll
        for (int half = 0; half < 2; half++) {
            int r = m0 + i*16 + tg + half*8;
            int lrow = row0 + r;
            if (lrow < M) {
                float* hrow = Hout + (size_t)lrow * NI + col0;
                #pragma unroll
                for (int jn = 0; jn < 4; jn++) {
                    float g0 = accg[i][jn][half*2+0], g1 = accg[i][jn][half*2+1];
                    float u0 = accu[i][jn][half*2+0], u1 = accu[i][jn][half*2+1];
                    float2 hv;
                    hv.x = g0 / (1.f + expf(-g0)) * u0;
                    hv.y = g1 / (1.f + expf(-g1)) * u1;
                    *reinterpret_cast<float2*>(hrow + n0 + jn*8 + 2*ti) = hv;
                }
            }
        }
    }
}

// ---------------- down GEMM (mma.sync tf32) ------------------------------------
// Block: M=128 x N=128. Warp tile 32(M) x 64(N). Expert rows scatter via pidlist.
template<bool EXPERT>
__global__ __launch_bounds__(256)
void down_mma(const float* __restrict__ Wd,    // [*, NI, NH] n-contiguous
              float* __restrict__ outp) {
    extern __shared__ float smem[];
    const int e    = EXPERT ? blockIdx.z : 0;
    const int M    = EXPERT ? g_cnt[e] : NT;
    const int row0 = blockIdx.y * 128;
    if (row0 >= M) return;
    const int col0 = blockIdx.x * 128;

    const float* A  = EXPERT ? (g_hbuf + (size_t)e * NT * NI) : g_shh;
    const float* wd = Wd + (EXPERT ? (size_t)e * NI * NH : (size_t)0);

    const int tid = threadIdx.x, wid = tid >> 5, lane = tid & 31;
    const uint32_t sbase = smem_u32(smem);

    const float* src;
    size_t sstep;
    int dst_off;
    if (tid < 128) {
        int r = tid;
        int ar = row0 + r; if (ar >= M) ar = M - 1;
        src = A + (size_t)ar * NI;
        sstep = KC;
        dst_off = r * DN_A_PAD;
    } else {
        int u = tid - 128, r = u >> 2, q = u & 3;
        src = wd + (size_t)r * NH + col0 + q * 32;
        sstep = (size_t)KC * NH;
        dst_off = DN_B_OFF + r * DN_B_PAD + q * 32;
    }

    float acc[2][8][4];
    #pragma unroll
    for (int i = 0; i < 2; i++)
        #pragma unroll
        for (int j = 0; j < 8; j++)
            #pragma unroll
            for (int q = 0; q < 4; q++) acc[i][j][q] = 0.f;

    const int m0 = (wid & 3) * 32, n0 = (wid >> 2) * 64;
    const int tg = lane >> 2, ti = lane & 3;

    #pragma unroll
    for (int s = 0; s < 2; s++) {
        uint32_t d = sbase + (uint32_t)(s * DN_STAGE_FLOATS + dst_off) * 4;
        #pragma unroll
        for (int c = 0; c < 8; c++) cpa16(d + c*16, src + c*4);
        cp_commit();
        src += sstep;
    }

    const int KST = NI / KC;   // 44
    for (int j = 0; j < KST; j++) {
        if (j < KST - 1) asm volatile("cp.async.wait_group 1;" ::: "memory");
        else             asm volatile("cp.async.wait_group 0;" ::: "memory");
        __syncthreads();
        if (j + 2 < KST) {
            int s = (j + 2) % 3;
            uint32_t d = sbase + (uint32_t)(s * DN_STAGE_FLOATS + dst_off) * 4;
            #pragma unroll
            for (int c = 0; c < 8; c++) cpa16(d + c*16, src + c*4);
            cp_commit();
            src += sstep;
        }
        const float* sA = smem + (j % 3) * DN_STAGE_FLOATS;
        const float* sB = sA + DN_B_OFF;
        #pragma unroll
        for (int kk = 0; kk < 4; kk++) {
            const int k0 = kk * 8;
            uint32_t a[2][4];
            #pragma unroll
            for (int i = 0; i < 2; i++) {
                int r = m0 + i*16 + tg;
                a[i][0] = ldrna(sA + (size_t)r     * DN_A_PAD + k0 + ti);
                a[i][1] = ldrna(sA + (size_t)(r+8) * DN_A_PAD + k0 + ti);
                a[i][2] = ldrna(sA + (size_t)r     * DN_A_PAD + k0 + 4 + ti);
                a[i][3] = ldrna(sA + (size_t)(r+8) * DN_A_PAD + k0 + 4 + ti);
            }
            #pragma unroll
            for (int jn = 0; jn < 8; jn++) {
                int n = n0 + jn*8 + tg;
                uint32_t b[2];
                b[0] = ldrna(sB + (size_t)(k0 + ti)     * DN_B_PAD + n);
                b[1] = ldrna(sB + (size_t)(k0 + 4 + ti) * DN_B_PAD + n);
                #pragma unroll
                for (int i = 0; i < 2; i++) mma_tf32(acc[i][jn], a[i], b);
            }
        }
    }

    #pragma unroll
    for (int i = 0; i < 2; i++) {
        #pragma unroll
        for (int half = 0; half < 2; half++) {
            int r = m0 + i*16 + tg + half*8;
            int lrow = row0 + r;
            if (lrow < M) {
                float* crow;
                if (EXPERT) crow = g_down + (size_t)g_pidlist[e*NT + lrow] * NH;
                else        crow = outp   + (size_t)lrow * NH;
                crow += col0 + n0;
                #pragma unroll
                for (int jn = 0; jn < 8; jn++) {
                    float2 v;
                    v.x = acc[i][jn][half*2+0];
                    v.y = acc[i][jn][half*2+1];
                    *reinterpret_cast<float2*>(crow + jn*8 + 2*ti) = v;
                }
            }
        }
    }
}

// ---------------- combine: out = shared + w0*d0 + w1*d1 ------------------------
__global__ void combine_kernel(float* __restrict__ outp) {
    int t = blockIdx.x;
    int i = threadIdx.x;
    float w0 = g_w[2*t], w1 = g_w[2*t+1];
    float4*       o = reinterpret_cast<float4*>(outp + (size_t)t * NH);
    const float4* a = reinterpret_cast<const float4*>(g_down + (size_t)(2*t)   * NH);
    const float4* b = reinterpret_cast<const float4*>(g_down + (size_t)(2*t+1) * NH);
    float4 ov = o[i], av = a[i], bv = b[i];
    ov.x = fmaf(w1, bv.x, fmaf(w0, av.x, ov.x));
    ov.y = fmaf(w1, bv.y, fmaf(w0, av.y, ov.y));
    ov.z = fmaf(w1, bv.z, fmaf(w0, av.z, ov.z));
    ov.w = fmaf(w1, bv.w, fmaf(w0, av.w, ov.w));
    o[i] = ov;
}

// ---------------- launch ---------------------------------------------------------
extern "C" void kernel_launch(void* const* d_in, const int* in_sizes, int n_in,
                              void* d_out, int out_size) {
    const float* x  = (const float*)d_in[0];
    const float* gw = (const float*)d_in[1];
    const float* eg = (const float*)d_in[2];
    const float* eu = (const float*)d_in[3];
    const float* ed = (const float*)d_in[4];
    const float* sg = (const float*)d_in[5];
    const float* su = (const float*)d_in[6];
    const float* sd = (const float*)d_in[7];
    float* out = (float*)d_out;

    static bool attr_done = false;
    if (!attr_done) {
        cudaFuncSetAttribute(gateup_mma<false>, cudaFuncAttributeMaxDynamicSharedMemorySize, GU_SMEM_BYTES);
        cudaFuncSetAttribute(gateup_mma<true>,  cudaFuncAttributeMaxDynamicSharedMemorySize, GU_SMEM_BYTES);
        cudaFuncSetAttribute(down_mma<false>,   cudaFuncAttributeMaxDynamicSharedMemorySize, DN_SMEM_BYTES);
        cudaFuncSetAttribute(down_mma<true>,    cudaFuncAttributeMaxDynamicSharedMemorySize, DN_SMEM_BYTES);
        attr_done = true;
    }

    zero_cnt_kernel<<<1, 32>>>();
    router_kernel<<<NT/4, 128>>>(x, gw);

    // gate+up SwiGLU
    gateup_mma<false><<<dim3(NI/64, NT/128, 1),  256, GU_SMEM_BYTES>>>(x, sg, su);
    gateup_mma<true> <<<dim3(NI/64, NT/128, NE), 256, GU_SMEM_BYTES>>>(x, eg, eu);

    // down projection
    down_mma<false><<<dim3(NH/128, NT/128, 1),  256, DN_SMEM_BYTES>>>(sd, out);
    down_mma<true> <<<dim3(NH/128, NT/128, NE), 256, DN_SMEM_BYTES>>>(ed, out);

    combine_kernel<<<NT, 256>>>(out);
}

// round 4
// speedup vs baseline: 1.9949x; 1.0551x over previous
#include <cuda_runtime.h>
#include <math.h>
#include <stdint.h>

// Problem dims (fixed)
#define NT 8192   // tokens
#define NH 1024   // hidden
#define NE 8      // experts
#define NI 1408   // intermediate

#define KC 32     // K per pipeline stage

// gateup stage layout (floats): A[128][36] + Bg[32][72] + Bu[32][72]
#define GU_A_PAD 36
#define GU_B_PAD 72
#define GU_A_FLOATS (128 * GU_A_PAD)
#define GU_BG_OFF   GU_A_FLOATS
#define GU_BU_OFF   (GU_A_FLOATS + 32 * GU_B_PAD)
#define GU_STAGE_FLOATS (GU_A_FLOATS + 2 * 32 * GU_B_PAD)   // 9216
#define GU_SMEM_BYTES (3 * GU_STAGE_FLOATS * 4)             // 110592

// down stage layout: A[128][36] + B[32][136]
#define DN_A_PAD 36
#define DN_B_PAD 136
#define DN_A_FLOATS (128 * DN_A_PAD)
#define DN_B_OFF    DN_A_FLOATS
#define DN_STAGE_FLOATS (DN_A_FLOATS + 32 * DN_B_PAD)       // 8960
#define DN_SMEM_BYTES (3 * DN_STAGE_FLOATS * 4)             // 107520

// ---------------- scratch (device globals) ----------------------------------
__device__ float g_xr [(size_t)NT*NH];          // tf32-rounded x
__device__ float g_egr[(size_t)NE*NH*NI];       // tf32-rounded weights
__device__ float g_eur[(size_t)NE*NH*NI];
__device__ float g_edr[(size_t)NE*NI*NH];
__device__ float g_sgr[(size_t)NH*NI];
__device__ float g_sur[(size_t)NH*NI];
__device__ float g_sdr[(size_t)NI*NH];
__device__ float g_hbuf[(size_t)NE*NT*NI];      // expert SwiGLU activations (tf32-rounded)
__device__ float g_shh [(size_t)NT*NI];         // shared SwiGLU activations (tf32-rounded)
__device__ float g_down[(size_t)2*NT*NH];       // per-(token,k) down outputs
__device__ int   g_rowlist[NE*NT];
__device__ int   g_pidlist[NE*NT];
__device__ int   g_cnt[NE];
__device__ float g_w[NT*2];

// ---------------- helpers ----------------------------------------------------
__device__ __forceinline__ uint32_t smem_u32(const void* p) {
    uint32_t a;
    asm("{ .reg .u64 t; cvta.to.shared.u64 t, %1; cvt.u32.u64 %0, t; }" : "=r"(a) : "l"(p));
    return a;
}
__device__ __forceinline__ void cpa16(uint32_t dst, const float* src) {
    asm volatile("cp.async.cg.shared.global [%0], [%1], 16;" :: "r"(dst), "l"(src) : "memory");
}
__device__ __forceinline__ void cp_commit() {
    asm volatile("cp.async.commit_group;" ::: "memory");
}
__device__ __forceinline__ float rna_tf32(float x) {
    asm("cvt.rna.tf32.f32 %0, %1;" : "=f"(x) : "f"(x));
    return x;
}
__device__ __forceinline__ void mma_tf32(float* c, const uint32_t* a, const uint32_t* b) {
    asm volatile(
        "mma.sync.aligned.m16n8k8.row.col.f32.tf32.tf32.f32 "
        "{%0,%1,%2,%3}, {%4,%5,%6,%7}, {%8,%9}, {%0,%1,%2,%3};"
        : "+f"(c[0]), "+f"(c[1]), "+f"(c[2]), "+f"(c[3])
        : "r"(a[0]), "r"(a[1]), "r"(a[2]), "r"(a[3]), "r"(b[0]), "r"(b[1]));
}
__device__ __forceinline__ uint32_t lds32(const float* p) {
    return __float_as_uint(*p);
}

// ---------------- small kernels ----------------------------------------------
__global__ void zero_cnt_kernel() {
    if (threadIdx.x < NE) g_cnt[threadIdx.x] = 0;
}

// elementwise tf32 round (float4)
__global__ void round_kernel(const float* __restrict__ in, float* __restrict__ out, int n4) {
    int i = blockIdx.x * blockDim.x + threadIdx.x;
    int stride = gridDim.x * blockDim.x;
    for (; i < n4; i += stride) {
        float4 v = reinterpret_cast<const float4*>(in)[i];
        v.x = rna_tf32(v.x); v.y = rna_tf32(v.y);
        v.z = rna_tf32(v.z); v.w = rna_tf32(v.w);
        reinterpret_cast<float4*>(out)[i] = v;
    }
}

// ---------------- router ------------------------------------------------------
__global__ void router_kernel(const float* __restrict__ x,
                              const float* __restrict__ gw) {
    int gtid = blockIdx.x * blockDim.x + threadIdx.x;
    int t    = gtid >> 5;
    int lane = gtid & 31;
    if (t >= NT) return;
    const float* xr = x + (size_t)t * NH;

    float acc[8] = {0.f,0.f,0.f,0.f,0.f,0.f,0.f,0.f};
    for (int h = lane; h < NH; h += 32) {
        float xv = __ldg(xr + h);
        const float4* g4 = reinterpret_cast<const float4*>(gw + (size_t)h * 8);
        float4 a = __ldg(g4 + 0);
        float4 b = __ldg(g4 + 1);
        acc[0] = fmaf(xv, a.x, acc[0]); acc[1] = fmaf(xv, a.y, acc[1]);
        acc[2] = fmaf(xv, a.z, acc[2]); acc[3] = fmaf(xv, a.w, acc[3]);
        acc[4] = fmaf(xv, b.x, acc[4]); acc[5] = fmaf(xv, b.y, acc[5]);
        acc[6] = fmaf(xv, b.z, acc[6]); acc[7] = fmaf(xv, b.w, acc[7]);
    }
    #pragma unroll
    for (int e = 0; e < 8; e++)
        #pragma unroll
        for (int off = 16; off > 0; off >>= 1)
            acc[e] += __shfl_xor_sync(0xffffffffu, acc[e], off);
    if (lane == 0) {
        float m = acc[0];
        #pragma unroll
        for (int e = 1; e < 8; e++) m = fmaxf(m, acc[e]);
        float p[8], s = 0.f;
        #pragma unroll
        for (int e = 0; e < 8; e++) { p[e] = expf(acc[e] - m); s += p[e]; }
        float inv = 1.f / s;
        #pragma unroll
        for (int e = 0; e < 8; e++) p[e] *= inv;
        int i0 = 0; float v0 = p[0];
        #pragma unroll
        for (int e = 1; e < 8; e++) if (p[e] > v0) { v0 = p[e]; i0 = e; }
        int i1 = -1; float v1 = -1.f;
        #pragma unroll
        for (int e = 0; e < 8; e++) if (e != i0 && p[e] > v1) { v1 = p[e]; i1 = e; }
        float denom = v0 + v1 + 1e-6f;
        g_w[2*t]   = v0 / denom;
        g_w[2*t+1] = v1 / denom;
        int r0 = atomicAdd(&g_cnt[i0], 1);
        g_rowlist[i0*NT + r0] = t; g_pidlist[i0*NT + r0] = 2*t;
        int r1 = atomicAdd(&g_cnt[i1], 1);
        g_rowlist[i1*NT + r1] = t; g_pidlist[i1*NT + r1] = 2*t + 1;
    }
}

// ---------------- gate+up SwiGLU GEMM (mma.sync tf32, pre-rounded inputs) -----
template<bool EXPERT>
__global__ __launch_bounds__(256, 2)
void gateup_mma(const float* __restrict__ Wg,   // rounded, [*, NH, NI]
                const float* __restrict__ Wu) {
    extern __shared__ float smem[];
    const int e    = EXPERT ? blockIdx.z : 0;
    const int M    = EXPERT ? g_cnt[e] : NT;
    const int row0 = blockIdx.y * 128;
    if (row0 >= M) return;
    const int col0 = blockIdx.x * 64;

    const float* wg = Wg + (EXPERT ? (size_t)e * NH * NI : (size_t)0);
    const float* wu = Wu + (EXPERT ? (size_t)e * NH * NI : (size_t)0);
    float* Hout = EXPERT ? (g_hbuf + (size_t)e * NT * NI) : g_shh;

    const int tid  = threadIdx.x, wid = tid >> 5, lane = tid & 31;
    const uint32_t sbase = smem_u32(smem);

    // per-thread cp.async role
    const float* src;
    size_t sstep;
    int dst_off;
    if (tid < 128) {
        int r = tid;
        int li = row0 + r; if (li >= M) li = M - 1;
        int gr = EXPERT ? g_rowlist[e*NT + li] : li;
        src = g_xr + (size_t)gr * NH;
        sstep = KC;
        dst_off = r * GU_A_PAD;
    } else if (tid < 192) {
        int u = tid - 128, r = u >> 1, half = u & 1;
        src = wg + (size_t)r * NI + col0 + half * 32;
        sstep = (size_t)KC * NI;
        dst_off = GU_BG_OFF + r * GU_B_PAD + half * 32;
    } else {
        int u = tid - 192, r = u >> 1, half = u & 1;
        src = wu + (size_t)r * NI + col0 + half * 32;
        sstep = (size_t)KC * NI;
        dst_off = GU_BU_OFF + r * GU_B_PAD + half * 32;
    }

    float accg[2][4][4], accu[2][4][4];
    #pragma unroll
    for (int i = 0; i < 2; i++)
        #pragma unroll
        for (int j = 0; j < 4; j++)
            #pragma unroll
            for (int q = 0; q < 4; q++) { accg[i][j][q] = 0.f; accu[i][j][q] = 0.f; }

    const int m0 = (wid & 3) * 32, n0 = (wid >> 2) * 32;
    const int tg = lane >> 2, ti = lane & 3;

    #pragma unroll
    for (int s = 0; s < 2; s++) {
        uint32_t d = sbase + (uint32_t)(s * GU_STAGE_FLOATS + dst_off) * 4;
        #pragma unroll
        for (int c = 0; c < 8; c++) cpa16(d + c*16, src + c*4);
        cp_commit();
        src += sstep;
    }

    const int KST = NH / KC;   // 32
    for (int j = 0; j < KST; j++) {
        if (j < KST - 1) asm volatile("cp.async.wait_group 1;" ::: "memory");
        else             asm volatile("cp.async.wait_group 0;" ::: "memory");
        __syncthreads();
        if (j + 2 < KST) {
            int s = (j + 2) % 3;
            uint32_t d = sbase + (uint32_t)(s * GU_STAGE_FLOATS + dst_off) * 4;
            #pragma unroll
            for (int c = 0; c < 8; c++) cpa16(d + c*16, src + c*4);
            cp_commit();
            src += sstep;
        }
        const float* sA  = smem + (j % 3) * GU_STAGE_FLOATS;
        const float* sBg = sA + GU_BG_OFF;
        const float* sBu = sA + GU_BU_OFF;
        #pragma unroll
        for (int kk = 0; kk < 4; kk++) {
            const int k0 = kk * 8;
            uint32_t a[2][4];
            #pragma unroll
            for (int i = 0; i < 2; i++) {
                int r = m0 + i*16 + tg;
                a[i][0] = lds32(sA + (size_t)r     * GU_A_PAD + k0 + ti);
                a[i][1] = lds32(sA + (size_t)(r+8) * GU_A_PAD + k0 + ti);
                a[i][2] = lds32(sA + (size_t)r     * GU_A_PAD + k0 + 4 + ti);
                a[i][3] = lds32(sA + (size_t)(r+8) * GU_A_PAD + k0 + 4 + ti);
            }
            #pragma unroll
            for (int jn = 0; jn < 4; jn++) {
                int n = n0 + jn*8 + tg;
                uint32_t bg[2], bu[2];
                bg[0] = lds32(sBg + (size_t)(k0 + ti)     * GU_B_PAD + n);
                bg[1] = lds32(sBg + (size_t)(k0 + 4 + ti) * GU_B_PAD + n);
                bu[0] = lds32(sBu + (size_t)(k0 + ti)     * GU_B_PAD + n);
                bu[1] = lds32(sBu + (size_t)(k0 + 4 + ti) * GU_B_PAD + n);
                #pragma unroll
                for (int i = 0; i < 2; i++) {
                    mma_tf32(accg[i][jn], a[i], bg);
                    mma_tf32(accu[i][jn], a[i], bu);
                }
            }
        }
    }

    // epilogue: silu(g)*u, round to tf32 (down-GEMM input), write rows
    #pragma unroll
    for (int i = 0; i < 2; i++) {
        #pragma unroll
        for (int half = 0; half < 2; half++) {
            int r = m0 + i*16 + tg + half*8;
            int lrow = row0 + r;
            if (lrow < M) {
                float* hrow = Hout + (size_t)lrow * NI + col0;
                #pragma unroll
                for (int jn = 0; jn < 4; jn++) {
                    float g0 = accg[i][jn][half*2+0], g1 = accg[i][jn][half*2+1];
                    float u0 = accu[i][jn][half*2+0], u1 = accu[i][jn][half*2+1];
                    float2 hv;
                    hv.x = rna_tf32(g0 / (1.f + expf(-g0)) * u0);
                    hv.y = rna_tf32(g1 / (1.f + expf(-g1)) * u1);
                    *reinterpret_cast<float2*>(hrow + n0 + jn*8 + 2*ti) = hv;
                }
            }
        }
    }
}

// ---------------- down GEMM (mma.sync tf32, pre-rounded inputs) ----------------
template<bool EXPERT>
__global__ __launch_bounds__(256, 2)
void down_mma(const float* __restrict__ Wd,    // rounded, [*, NI, NH]
              float* __restrict__ outp) {
    extern __shared__ float smem[];
    const int e    = EXPERT ? blockIdx.z : 0;
    const int M    = EXPERT ? g_cnt[e] : NT;
    const int row0 = blockIdx.y * 128;
    if (row0 >= M) return;
    const int col0 = blockIdx.x * 128;

    const float* A  = EXPERT ? (g_hbuf + (size_t)e * NT * NI) : g_shh;
    const float* wd = Wd + (EXPERT ? (size_t)e * NI * NH : (size_t)0);

    const int tid = threadIdx.x, wid = tid >> 5, lane = tid & 31;
    const uint32_t sbase = smem_u32(smem);

    const float* src;
    size_t sstep;
    int dst_off;
    if (tid < 128) {
        int r = tid;
        int ar = row0 + r; if (ar >= M) ar = M - 1;
        src = A + (size_t)ar * NI;
        sstep = KC;
        dst_off = r * DN_A_PAD;
    } else {
        int u = tid - 128, r = u >> 2, q = u & 3;
        src = wd + (size_t)r * NH + col0 + q * 32;
        sstep = (size_t)KC * NH;
        dst_off = DN_B_OFF + r * DN_B_PAD + q * 32;
    }

    float acc[2][8][4];
    #pragma unroll
    for (int i = 0; i < 2; i++)
        #pragma unroll
        for (int j = 0; j < 8; j++)
            #pragma unroll
            for (int q = 0; q < 4; q++) acc[i][j][q] = 0.f;

    const int m0 = (wid & 3) * 32, n0 = (wid >> 2) * 64;
    const int tg = lane >> 2, ti = lane & 3;

    #pragma unroll
    for (int s = 0; s < 2; s++) {
        uint32_t d = sbase + (uint32_t)(s * DN_STAGE_FLOATS + dst_off) * 4;
        #pragma unroll
        for (int c = 0; c < 8; c++) cpa16(d + c*16, src + c*4);
        cp_commit();
        src += sstep;
    }

    const int KST = NI / KC;   // 44
    for (int j = 0; j < KST; j++) {
        if (j < KST - 1) asm volatile("cp.async.wait_group 1;" ::: "memory");
        else             asm volatile("cp.async.wait_group 0;" ::: "memory");
        __syncthreads();
        if (j + 2 < KST) {
            int s = (j + 2) % 3;
            uint32_t d = sbase + (uint32_t)(s * DN_STAGE_FLOATS + dst_off) * 4;
            #pragma unroll
            for (int c = 0; c < 8; c++) cpa16(d + c*16, src + c*4);
            cp_commit();
            src += sstep;
        }
        const float* sA = smem + (j % 3) * DN_STAGE_FLOATS;
        const float* sB = sA + DN_B_OFF;
        #pragma unroll
        for (int kk = 0; kk < 4; kk++) {
            const int k0 = kk * 8;
            uint32_t a[2][4];
            #pragma unroll
            for (int i = 0; i < 2; i++) {
                int r = m0 + i*16 + tg;
                a[i][0] = lds32(sA + (size_t)r     * DN_A_PAD + k0 + ti);
                a[i][1] = lds32(sA + (size_t)(r+8) * DN_A_PAD + k0 + ti);
                a[i][2] = lds32(sA + (size_t)r     * DN_A_PAD + k0 + 4 + ti);
                a[i][3] = lds32(sA + (size_t)(r+8) * DN_A_PAD + k0 + 4 + ti);
            }
            #pragma unroll
            for (int jn = 0; jn < 8; jn++) {
                int n = n0 + jn*8 + tg;
                uint32_t b[2];
                b[0] = lds32(sB + (size_t)(k0 + ti)     * DN_B_PAD + n);
                b[1] = lds32(sB + (size_t)(k0 + 4 + ti) * DN_B_PAD + n);
                #pragma unroll
                for (int i = 0; i < 2; i++) mma_tf32(acc[i][jn], a[i], b);
            }
        }
    }

    #pragma unroll
    for (int i = 0; i < 2; i++) {
        #pragma unroll
        for (int half = 0; half < 2; half++) {
            int r = m0 + i*16 + tg + half*8;
            int lrow = row0 + r;
            if (lrow < M) {
                float* crow;
                if (EXPERT) crow = g_down + (size_t)g_pidlist[e*NT + lrow] * NH;
                else        crow = outp   + (size_t)lrow * NH;
                crow += col0 + n0;
                #pragma unroll
                for (int jn = 0; jn < 8; jn++) {
                    float2 v;
                    v.x = acc[i][jn][half*2+0];
                    v.y = acc[i][jn][half*2+1];
                    *reinterpret_cast<float2*>(crow + jn*8 + 2*ti) = v;
                }
            }
        }
    }
}

// ---------------- combine -------------------------------------------------------
__global__ void combine_kernel(float* __restrict__ outp) {
    int t = blockIdx.x;
    int i = threadIdx.x;
    float w0 = g_w[2*t], w1 = g_w[2*t+1];
    float4*       o = reinterpret_cast<float4*>(outp + (size_t)t * NH);
    const float4* a = reinterpret_cast<const float4*>(g_down + (size_t)(2*t)   * NH);
    const float4* b = reinterpret_cast<const float4*>(g_down + (size_t)(2*t+1) * NH);
    float4 ov = o[i], av = a[i], bv = b[i];
    ov.x = fmaf(w1, bv.x, fmaf(w0, av.x, ov.x));
    ov.y = fmaf(w1, bv.y, fmaf(w0, av.y, ov.y));
    ov.z = fmaf(w1, bv.z, fmaf(w0, av.z, ov.z));
    ov.w = fmaf(w1, bv.w, fmaf(w0, av.w, ov.w));
    o[i] = ov;
}

// ---------------- launch ----------------------------------------------------------
extern "C" void kernel_launch(void* const* d_in, const int* in_sizes, int n_in,
                              void* d_out, int out_size) {
    const float* x  = (const float*)d_in[0];
    const float* gw = (const float*)d_in[1];
    const float* eg = (const float*)d_in[2];
    const float* eu = (const float*)d_in[3];
    const float* ed = (const float*)d_in[4];
    const float* sg = (const float*)d_in[5];
    const float* su = (const float*)d_in[6];
    const float* sd = (const float*)d_in[7];
    float* out = (float*)d_out;

    static bool attr_done = false;
    if (!attr_done) {
        cudaFuncSetAttribute(gateup_mma<false>, cudaFuncAttributeMaxDynamicSharedMemorySize, GU_SMEM_BYTES);
        cudaFuncSetAttribute(gateup_mma<true>,  cudaFuncAttributeMaxDynamicSharedMemorySize, GU_SMEM_BYTES);
        cudaFuncSetAttribute(down_mma<false>,   cudaFuncAttributeMaxDynamicSharedMemorySize, DN_SMEM_BYTES);
        cudaFuncSetAttribute(down_mma<true>,    cudaFuncAttributeMaxDynamicSharedMemorySize, DN_SMEM_BYTES);
        attr_done = true;
    }

    float *p_xr, *p_egr, *p_eur, *p_edr, *p_sgr, *p_sur, *p_sdr;
    cudaGetSymbolAddress((void**)&p_xr,  g_xr);
    cudaGetSymbolAddress((void**)&p_egr, g_egr);
    cudaGetSymbolAddress((void**)&p_eur, g_eur);
    cudaGetSymbolAddress((void**)&p_edr, g_edr);
    cudaGetSymbolAddress((void**)&p_sgr, g_sgr);
    cudaGetSymbolAddress((void**)&p_sur, g_sur);
    cudaGetSymbolAddress((void**)&p_sdr, g_sdr);

    zero_cnt_kernel<<<1, 32>>>();
    router_kernel<<<NT/4, 128>>>(x, gw);

    // tf32 pre-round (makes HW mma conversion an identity)
    round_kernel<<<512, 256>>>(x,  p_xr,  NT*NH/4);
    round_kernel<<<2048, 256>>>(eg, p_egr, NE*NH*NI/4);
    round_kernel<<<2048, 256>>>(eu, p_eur, NE*NH*NI/4);
    round_kernel<<<2048, 256>>>(ed, p_edr, NE*NI*NH/4);
    round_kernel<<<512, 256>>>(sg, p_sgr, NH*NI/4);
    round_kernel<<<512, 256>>>(su, p_sur, NH*NI/4);
    round_kernel<<<512, 256>>>(sd, p_sdr, NI*NH/4);

    // gate+up SwiGLU
    gateup_mma<false><<<dim3(NI/64, NT/128, 1),  256, GU_SMEM_BYTES>>>(p_sgr, p_sur);
    gateup_mma<true> <<<dim3(NI/64, NT/128, NE), 256, GU_SMEM_BYTES>>>(p_egr, p_eur);

    // down projection
    down_mma<false><<<dim3(NH/128, NT/128, 1),  256, DN_SMEM_BYTES>>>(p_sdr, out);
    down_mma<true> <<<dim3(NH/128, NT/128, NE), 256, DN_SMEM_BYTES>>>(p_edr, out);

    combine_kernel<<<NT, 256>>>(out);
}

// round 5
// speedup vs baseline: 2.1364x; 1.0709x over previous
#include <cuda_runtime.h>
#include <math.h>
#include <stdint.h>

// Problem dims (fixed)
#define NT 8192   // tokens
#define NH 1024   // hidden
#define NE 8      // experts
#define NI 1408   // intermediate

#define KC 32     // K per pipeline stage
#define NSTAGE 4

// gateup stage layout (floats): A[128][36] + Bg[32][136] + Bu[32][136]
#define GU_A_PAD 36
#define GU_B_PAD 136
#define GU_BG_OFF (128 * GU_A_PAD)                       // 4608
#define GU_BU_OFF (GU_BG_OFF + 32 * GU_B_PAD)            // 8960
#define GU_STAGE_FLOATS (GU_BU_OFF + 32 * GU_B_PAD)      // 13312
#define GU_SMEM_BYTES (NSTAGE * GU_STAGE_FLOATS * 4)     // 212992

// down stage layout: A[128][36] + B[32][264]
#define DN_A_PAD 36
#define DN_B_PAD 264
#define DN_B_OFF  (128 * DN_A_PAD)                       // 4608
#define DN_STAGE_FLOATS (DN_B_OFF + 32 * DN_B_PAD)       // 13056
#define DN_SMEM_BYTES (NSTAGE * DN_STAGE_FLOATS * 4)     // 208896

// ---------------- scratch (device globals) ----------------------------------
__device__ float g_xr [(size_t)NT*NH];          // tf32-rounded x
__device__ float g_egr[(size_t)NE*NH*NI];       // tf32-rounded weights
__device__ float g_eur[(size_t)NE*NH*NI];
__device__ float g_edr[(size_t)NE*NI*NH];
__device__ float g_sgr[(size_t)NH*NI];
__device__ float g_sur[(size_t)NH*NI];
__device__ float g_sdr[(size_t)NI*NH];
__device__ float g_hbuf[(size_t)NE*NT*NI];      // expert SwiGLU activations (rounded)
__device__ float g_shh [(size_t)NT*NI];         // shared SwiGLU activations (rounded)
__device__ float g_down[(size_t)2*NT*NH];       // per-(token,k) down outputs
__device__ int   g_rowlist[NE*NT];
__device__ int   g_pidlist[NE*NT];
__device__ int   g_cnt[NE];
__device__ float g_w[NT*2];

// ---------------- helpers ----------------------------------------------------
__device__ __forceinline__ uint32_t smem_u32(const void* p) {
    uint32_t a;
    asm("{ .reg .u64 t; cvta.to.shared.u64 t, %1; cvt.u32.u64 %0, t; }" : "=r"(a) : "l"(p));
    return a;
}
__device__ __forceinline__ void cpa16(uint32_t dst, const float* src) {
    asm volatile("cp.async.cg.shared.global [%0], [%1], 16;" :: "r"(dst), "l"(src) : "memory");
}
__device__ __forceinline__ void cp_commit() {
    asm volatile("cp.async.commit_group;" ::: "memory");
}
__device__ __forceinline__ float rna_tf32(float x) {
    asm("cvt.rna.tf32.f32 %0, %1;" : "=f"(x) : "f"(x));
    return x;
}
__device__ __forceinline__ void mma_tf32(float* c, const uint32_t* a, const uint32_t* b) {
    asm volatile(
        "mma.sync.aligned.m16n8k8.row.col.f32.tf32.tf32.f32 "
        "{%0,%1,%2,%3}, {%4,%5,%6,%7}, {%8,%9}, {%0,%1,%2,%3};"
        : "+f"(c[0]), "+f"(c[1]), "+f"(c[2]), "+f"(c[3])
        : "r"(a[0]), "r"(a[1]), "r"(a[2]), "r"(a[3]), "r"(b[0]), "r"(b[1]));
}
__device__ __forceinline__ uint32_t lds32(const float* p) {
    return __float_as_uint(*p);
}

// ---------------- small kernels ----------------------------------------------
__global__ void zero_cnt_kernel() {
    if (threadIdx.x < NE) g_cnt[threadIdx.x] = 0;
}

__global__ void round_kernel(const float* __restrict__ in, float* __restrict__ out, int n4) {
    int i = blockIdx.x * blockDim.x + threadIdx.x;
    int stride = gridDim.x * blockDim.x;
    for (; i < n4; i += stride) {
        float4 v = reinterpret_cast<const float4*>(in)[i];
        v.x = rna_tf32(v.x); v.y = rna_tf32(v.y);
        v.z = rna_tf32(v.z); v.w = rna_tf32(v.w);
        reinterpret_cast<float4*>(out)[i] = v;
    }
}

// ---------------- router ------------------------------------------------------
__global__ void router_kernel(const float* __restrict__ x,
                              const float* __restrict__ gw) {
    int gtid = blockIdx.x * blockDim.x + threadIdx.x;
    int t    = gtid >> 5;
    int lane = gtid & 31;
    if (t >= NT) return;
    const float* xr = x + (size_t)t * NH;

    float acc[8] = {0.f,0.f,0.f,0.f,0.f,0.f,0.f,0.f};
    for (int h = lane; h < NH; h += 32) {
        float xv = __ldg(xr + h);
        const float4* g4 = reinterpret_cast<const float4*>(gw + (size_t)h * 8);
        float4 a = __ldg(g4 + 0);
        float4 b = __ldg(g4 + 1);
        acc[0] = fmaf(xv, a.x, acc[0]); acc[1] = fmaf(xv, a.y, acc[1]);
        acc[2] = fmaf(xv, a.z, acc[2]); acc[3] = fmaf(xv, a.w, acc[3]);
        acc[4] = fmaf(xv, b.x, acc[4]); acc[5] = fmaf(xv, b.y, acc[5]);
        acc[6] = fmaf(xv, b.z, acc[6]); acc[7] = fmaf(xv, b.w, acc[7]);
    }
    #pragma unroll
    for (int e = 0; e < 8; e++)
        #pragma unroll
        for (int off = 16; off > 0; off >>= 1)
            acc[e] += __shfl_xor_sync(0xffffffffu, acc[e], off);
    if (lane == 0) {
        float m = acc[0];
        #pragma unroll
        for (int e = 1; e < 8; e++) m = fmaxf(m, acc[e]);
        float p[8], s = 0.f;
        #pragma unroll
        for (int e = 0; e < 8; e++) { p[e] = expf(acc[e] - m); s += p[e]; }
        float inv = 1.f / s;
        #pragma unroll
        for (int e = 0; e < 8; e++) p[e] *= inv;
        int i0 = 0; float v0 = p[0];
        #pragma unroll
        for (int e = 1; e < 8; e++) if (p[e] > v0) { v0 = p[e]; i0 = e; }
        int i1 = -1; float v1 = -1.f;
        #pragma unroll
        for (int e = 0; e < 8; e++) if (e != i0 && p[e] > v1) { v1 = p[e]; i1 = e; }
        float denom = v0 + v1 + 1e-6f;
        g_w[2*t]   = v0 / denom;
        g_w[2*t+1] = v1 / denom;
        int r0 = atomicAdd(&g_cnt[i0], 1);
        g_rowlist[i0*NT + r0] = t; g_pidlist[i0*NT + r0] = 2*t;
        int r1 = atomicAdd(&g_cnt[i1], 1);
        g_rowlist[i1*NT + r1] = t; g_pidlist[i1*NT + r1] = 2*t + 1;
    }
}

// ---------------- gate+up SwiGLU GEMM ----------------------------------------
// Block 128(M) x 128(N for each of gate/up). 8 warps, warp tile 64x32 per matrix.
template<bool EXPERT>
__global__ __launch_bounds__(256, 1)
void gateup_mma(const float* __restrict__ Wg,   // rounded, [*, NH, NI]
                const float* __restrict__ Wu) {
    extern __shared__ float smem[];
    const int e    = EXPERT ? blockIdx.z : 0;
    const int M    = EXPERT ? g_cnt[e] : NT;
    const int row0 = blockIdx.y * 128;
    if (row0 >= M) return;
    const int col0 = blockIdx.x * 128;

    const float* wg = Wg + (EXPERT ? (size_t)e * NH * NI : (size_t)0);
    const float* wu = Wu + (EXPERT ? (size_t)e * NH * NI : (size_t)0);
    float* Hout = EXPERT ? (g_hbuf + (size_t)e * NT * NI) : g_shh;

    const int tid = threadIdx.x, wid = tid >> 5, lane = tid & 31;
    const uint32_t sbase = smem_u32(smem);

    // per-thread cp.async role
    const float* src;
    size_t sstep;
    int dst_off, nchunk;
    if (tid < 128) {
        int r = tid;
        int li = row0 + r; if (li >= M) li = M - 1;
        int gr = EXPERT ? g_rowlist[e*NT + li] : li;
        src = g_xr + (size_t)gr * NH;
        sstep = KC;
        dst_off = r * GU_A_PAD;
        nchunk = 8;
    } else if (tid < 192) {
        int u = tid - 128, r = u >> 1, half = u & 1;
        src = wg + (size_t)r * NI + col0 + half * 64;
        sstep = (size_t)KC * NI;
        dst_off = GU_BG_OFF + r * GU_B_PAD + half * 64;
        nchunk = 16;
    } else {
        int u = tid - 192, r = u >> 1, half = u & 1;
        src = wu + (size_t)r * NI + col0 + half * 64;
        sstep = (size_t)KC * NI;
        dst_off = GU_BU_OFF + r * GU_B_PAD + half * 64;
        nchunk = 16;
    }

    float accg[4][4][4], accu[4][4][4];
    #pragma unroll
    for (int i = 0; i < 4; i++)
        #pragma unroll
        for (int j = 0; j < 4; j++)
            #pragma unroll
            for (int q = 0; q < 4; q++) { accg[i][j][q] = 0.f; accu[i][j][q] = 0.f; }

    const int m0 = (wid & 1) * 64, n0 = (wid >> 1) * 32;
    const int tg = lane >> 2, ti = lane & 3;

    // prologue: stages 0..2
    #pragma unroll
    for (int s = 0; s < NSTAGE - 1; s++) {
        uint32_t d = sbase + (uint32_t)(s * GU_STAGE_FLOATS + dst_off) * 4;
        for (int c = 0; c < nchunk; c++) cpa16(d + c*16, src + c*4);
        cp_commit();
        src += sstep;
    }

    const int KST = NH / KC;   // 32
    for (int j = 0; j < KST; j++) {
        if      (j + 3 <= KST - 1) asm volatile("cp.async.wait_group 2;" ::: "memory");
        else if (j + 2 <= KST - 1) asm volatile("cp.async.wait_group 1;" ::: "memory");
        else                       asm volatile("cp.async.wait_group 0;" ::: "memory");
        __syncthreads();
        if (j + NSTAGE - 1 < KST) {
            int s = (j + NSTAGE - 1) % NSTAGE;
            uint32_t d = sbase + (uint32_t)(s * GU_STAGE_FLOATS + dst_off) * 4;
            for (int c = 0; c < nchunk; c++) cpa16(d + c*16, src + c*4);
            cp_commit();
            src += sstep;
        }
        const float* sA  = smem + (j % NSTAGE) * GU_STAGE_FLOATS;
        const float* sBg = sA + GU_BG_OFF;
        const float* sBu = sA + GU_BU_OFF;
        #pragma unroll
        for (int kk = 0; kk < 4; kk++) {
            const int k0 = kk * 8;
            uint32_t a[4][4];
            #pragma unroll
            for (int i = 0; i < 4; i++) {
                int r = m0 + i*16 + tg;
                a[i][0] = lds32(sA + (size_t)r     * GU_A_PAD + k0 + ti);
                a[i][1] = lds32(sA + (size_t)(r+8) * GU_A_PAD + k0 + ti);
                a[i][2] = lds32(sA + (size_t)r     * GU_A_PAD + k0 + 4 + ti);
                a[i][3] = lds32(sA + (size_t)(r+8) * GU_A_PAD + k0 + 4 + ti);
            }
            #pragma unroll
            for (int jn = 0; jn < 4; jn++) {
                int n = n0 + jn*8 + tg;
                uint32_t bg[2], bu[2];
                bg[0] = lds32(sBg + (size_t)(k0 + ti)     * GU_B_PAD + n);
                bg[1] = lds32(sBg + (size_t)(k0 + 4 + ti) * GU_B_PAD + n);
                bu[0] = lds32(sBu + (size_t)(k0 + ti)     * GU_B_PAD + n);
                bu[1] = lds32(sBu + (size_t)(k0 + 4 + ti) * GU_B_PAD + n);
                #pragma unroll
                for (int i = 0; i < 4; i++) {
                    mma_tf32(accg[i][jn], a[i], bg);
                    mma_tf32(accu[i][jn], a[i], bu);
                }
            }
        }
    }

    // epilogue: silu(g)*u, round to tf32, write
    #pragma unroll
    for (int i = 0; i < 4; i++) {
        #pragma unroll
        for (int half = 0; half < 2; half++) {
            int r = m0 + i*16 + half*8 + tg;
            int lrow = row0 + r;
            if (lrow < M) {
                float* hrow = Hout + (size_t)lrow * NI + col0 + n0;
                #pragma unroll
                for (int jn = 0; jn < 4; jn++) {
                    float g0 = accg[i][jn][half*2+0], g1 = accg[i][jn][half*2+1];
                    float u0 = accu[i][jn][half*2+0], u1 = accu[i][jn][half*2+1];
                    float2 hv;
                    hv.x = rna_tf32(g0 / (1.f + expf(-g0)) * u0);
                    hv.y = rna_tf32(g1 / (1.f + expf(-g1)) * u1);
                    *reinterpret_cast<float2*>(hrow + jn*8 + 2*ti) = hv;
                }
            }
        }
    }
}

// ---------------- down GEMM ----------------------------------------------------
// Block 128(M) x 256(N). 8 warps, warp tile 64x64.
template<bool EXPERT>
__global__ __launch_bounds__(256, 1)
void down_mma(const float* __restrict__ Wd,    // rounded, [*, NI, NH]
              float* __restrict__ outp) {
    extern __shared__ float smem[];
    const int e    = EXPERT ? blockIdx.z : 0;
    const int M    = EXPERT ? g_cnt[e] : NT;
    const int row0 = blockIdx.y * 128;
    if (row0 >= M) return;
    const int col0 = blockIdx.x * 256;

    const float* A  = EXPERT ? (g_hbuf + (size_t)e * NT * NI) : g_shh;
    const float* wd = Wd + (EXPERT ? (size_t)e * NI * NH : (size_t)0);

    const int tid = threadIdx.x, wid = tid >> 5, lane = tid & 31;
    const uint32_t sbase = smem_u32(smem);

    const float* src;
    size_t sstep;
    int dst_off, nchunk;
    if (tid < 128) {
        int r = tid;
        int ar = row0 + r; if (ar >= M) ar = M - 1;
        src = A + (size_t)ar * NI;
        sstep = KC;
        dst_off = r * DN_A_PAD;
        nchunk = 8;
    } else {
        int u = tid - 128, r = u >> 2, q = u & 3;
        src = wd + (size_t)r * NH + col0 + q * 64;
        sstep = (size_t)KC * NH;
        dst_off = DN_B_OFF + r * DN_B_PAD + q * 64;
        nchunk = 16;
    }

    float acc[4][8][4];
    #pragma unroll
    for (int i = 0; i < 4; i++)
        #pragma unroll
        for (int j = 0; j < 8; j++)
            #pragma unroll
            for (int q = 0; q < 4; q++) acc[i][j][q] = 0.f;

    const int m0 = (wid & 1) * 64, n0 = (wid >> 1) * 64;
    const int tg = lane >> 2, ti = lane & 3;

    #pragma unroll
    for (int s = 0; s < NSTAGE - 1; s++) {
        uint32_t d = sbase + (uint32_t)(s * DN_STAGE_FLOATS + dst_off) * 4;
        for (int c = 0; c < nchunk; c++) cpa16(d + c*16, src + c*4);
        cp_commit();
        src += sstep;
    }

    const int KST = NI / KC;   // 44
    for (int j = 0; j < KST; j++) {
        if      (j + 3 <= KST - 1) asm volatile("cp.async.wait_group 2;" ::: "memory");
        else if (j + 2 <= KST - 1) asm volatile("cp.async.wait_group 1;" ::: "memory");
        else                       asm volatile("cp.async.wait_group 0;" ::: "memory");
        __syncthreads();
        if (j + NSTAGE - 1 < KST) {
            int s = (j + NSTAGE - 1) % NSTAGE;
            uint32_t d = sbase + (uint32_t)(s * DN_STAGE_FLOATS + dst_off) * 4;
            for (int c = 0; c < nchunk; c++) cpa16(d + c*16, src + c*4);
            cp_commit();
            src += sstep;
        }
        const float* sA = smem + (j % NSTAGE) * DN_STAGE_FLOATS;
        const float* sB = sA + DN_B_OFF;
        #pragma unroll
        for (int kk = 0; kk < 4; kk++) {
            const int k0 = kk * 8;
            uint32_t a[4][4];
            #pragma unroll
            for (int i = 0; i < 4; i++) {
                int r = m0 + i*16 + tg;
                a[i][0] = lds32(sA + (size_t)r     * DN_A_PAD + k0 + ti);
                a[i][1] = lds32(sA + (size_t)(r+8) * DN_A_PAD + k0 + ti);
                a[i][2] = lds32(sA + (size_t)r     * DN_A_PAD + k0 + 4 + ti);
                a[i][3] = lds32(sA + (size_t)(r+8) * DN_A_PAD + k0 + 4 + ti);
            }
            #pragma unroll
            for (int jn = 0; jn < 8; jn++) {
                int n = n0 + jn*8 + tg;
                uint32_t b[2];
                b[0] = lds32(sB + (size_t)(k0 + ti)     * DN_B_PAD + n);
                b[1] = lds32(sB + (size_t)(k0 + 4 + ti) * DN_B_PAD + n);
                #pragma unroll
                for (int i = 0; i < 4; i++) mma_tf32(acc[i][jn], a[i], b);
            }
        }
    }

    #pragma unroll
    for (int i = 0; i < 4; i++) {
        #pragma unroll
        for (int half = 0; half < 2; half++) {
            int r = m0 + i*16 + half*8 + tg;
            int lrow = row0 + r;
            if (lrow < M) {
                float* crow;
                if (EXPERT) crow = g_down + (size_t)g_pidlist[e*NT + lrow] * NH;
                else        crow = outp   + (size_t)lrow * NH;
                crow += col0 + n0;
                #pragma unroll
                for (int jn = 0; jn < 8; jn++) {
                    float2 v;
                    v.x = acc[i][jn][half*2+0];
                    v.y = acc[i][jn][half*2+1];
                    *reinterpret_cast<float2*>(crow + jn*8 + 2*ti) = v;
                }
            }
        }
    }
}

// ---------------- combine -------------------------------------------------------
__global__ void combine_kernel(float* __restrict__ outp) {
    int t = blockIdx.x;
    int i = threadIdx.x;
    float w0 = g_w[2*t], w1 = g_w[2*t+1];
    float4*       o = reinterpret_cast<float4*>(outp + (size_t)t * NH);
    const float4* a = reinterpret_cast<const float4*>(g_down + (size_t)(2*t)   * NH);
    const float4* b = reinterpret_cast<const float4*>(g_down + (size_t)(2*t+1) * NH);
    float4 ov = o[i], av = a[i], bv = b[i];
    ov.x = fmaf(w1, bv.x, fmaf(w0, av.x, ov.x));
    ov.y = fmaf(w1, bv.y, fmaf(w0, av.y, ov.y));
    ov.z = fmaf(w1, bv.z, fmaf(w0, av.z, ov.z));
    ov.w = fmaf(w1, bv.w, fmaf(w0, av.w, ov.w));
    o[i] = ov;
}

// ---------------- launch ----------------------------------------------------------
extern "C" void kernel_launch(void* const* d_in, const int* in_sizes, int n_in,
                              void* d_out, int out_size) {
    const float* x  = (const float*)d_in[0];
    const float* gw = (const float*)d_in[1];
    const float* eg = (const float*)d_in[2];
    const float* eu = (const float*)d_in[3];
    const float* ed = (const float*)d_in[4];
    const float* sg = (const float*)d_in[5];
    const float* su = (const float*)d_in[6];
    const float* sd = (const float*)d_in[7];
    float* out = (float*)d_out;

    static bool attr_done = false;
    if (!attr_done) {
        cudaFuncSetAttribute(gateup_mma<false>, cudaFuncAttributeMaxDynamicSharedMemorySize, GU_SMEM_BYTES);
        cudaFuncSetAttribute(gateup_mma<true>,  cudaFuncAttributeMaxDynamicSharedMemorySize, GU_SMEM_BYTES);
        cudaFuncSetAttribute(down_mma<false>,   cudaFuncAttributeMaxDynamicSharedMemorySize, DN_SMEM_BYTES);
        cudaFuncSetAttribute(down_mma<true>,    cudaFuncAttributeMaxDynamicSharedMemorySize, DN_SMEM_BYTES);
        attr_done = true;
    }

    float *p_xr, *p_egr, *p_eur, *p_edr, *p_sgr, *p_sur, *p_sdr;
    cudaGetSymbolAddress((void**)&p_xr,  g_xr);
    cudaGetSymbolAddress((void**)&p_egr, g_egr);
    cudaGetSymbolAddress((void**)&p_eur, g_eur);
    cudaGetSymbolAddress((void**)&p_edr, g_edr);
    cudaGetSymbolAddress((void**)&p_sgr, g_sgr);
    cudaGetSymbolAddress((void**)&p_sur, g_sur);
    cudaGetSymbolAddress((void**)&p_sdr, g_sdr);

    zero_cnt_kernel<<<1, 32>>>();
    router_kernel<<<NT/4, 128>>>(x, gw);

    // tf32 pre-round (makes HW mma conversion an identity)
    round_kernel<<<512, 256>>>(x,  p_xr,  NT*NH/4);
    round_kernel<<<2048, 256>>>(eg, p_egr, NE*NH*NI/4);
    round_kernel<<<2048, 256>>>(eu, p_eur, NE*NH*NI/4);
    round_kernel<<<2048, 256>>>(ed, p_edr, NE*NI*NH/4);
    round_kernel<<<512, 256>>>(sg, p_sgr, NH*NI/4);
    round_kernel<<<512, 256>>>(su, p_sur, NH*NI/4);
    round_kernel<<<512, 256>>>(sd, p_sdr, NI*NH/4);

    // gate+up SwiGLU
    gateup_mma<false><<<dim3(NI/128, NT/128, 1),  256, GU_SMEM_BYTES>>>(p_sgr, p_sur);
    gateup_mma<true> <<<dim3(NI/128, NT/128, NE), 256, GU_SMEM_BYTES>>>(p_egr, p_eur);

    // down projection
    down_mma<false><<<dim3(NH/256, NT/128, 1),  256, DN_SMEM_BYTES>>>(p_sdr, out);
    down_mma<true> <<<dim3(NH/256, NT/128, NE), 256, DN_SMEM_BYTES>>>(p_edr, out);

    combine_kernel<<<NT, 256>>>(out);
}

// round 6
// speedup vs baseline: 3.9338x; 1.8413x over previous
#include <cuda_runtime.h>
#include <cuda_fp16.h>
#include <math.h>
#include <stdint.h>

// Problem dims (fixed)
#define NT 8192   // tokens
#define NH 1024   // hidden
#define NE 8      // experts
#define NI 1408   // intermediate

#define KC 64     // K halfs per pipeline stage (128B rows)
#define NSTAGE 3
#define PADH 72   // halfs per smem row (36 words: lane word = tg*4+ti, conflict-free)

// gateup stage (halfs): A[128][72] + Bg[128][72] + Bu[128][72]
#define GU_BG_OFF (128 * PADH)
#define GU_BU_OFF (256 * PADH)
#define GU_STAGE  (384 * PADH)                       // 27648 halfs
#define GU_SMEM_BYTES (NSTAGE * GU_STAGE * 2)        // 165888

// down stage (halfs): A[128][72] + B[256][72]
#define DN_B_OFF  (128 * PADH)
#define DN_STAGE  (384 * PADH)                       // 27648 halfs
#define DN_SMEM_BYTES (NSTAGE * DN_STAGE * 2)        // 165888

// ---------------- scratch (device globals) ----------------------------------
__device__ __half g_xh [(size_t)NT*NH];          // fp16 x, row-major (k-contig)
__device__ __half g_egT[(size_t)NE*NI*NH];       // fp16 weights, transposed: [N][K]
__device__ __half g_euT[(size_t)NE*NI*NH];
__device__ __half g_edT[(size_t)NE*NH*NI];
__device__ __half g_sgT[(size_t)NI*NH];
__device__ __half g_suT[(size_t)NI*NH];
__device__ __half g_sdT[(size_t)NH*NI];
__device__ __half g_hbuf[(size_t)NE*NT*NI];      // expert SwiGLU activations (fp16)
__device__ __half g_shh [(size_t)NT*NI];         // shared SwiGLU activations (fp16)
__device__ float  g_down[(size_t)2*NT*NH];       // per-(token,k) down outputs (fp32)
__device__ int    g_rowlist[NE*NT];
__device__ int    g_pidlist[NE*NT];
__device__ int    g_cnt[NE];
__device__ float  g_w[NT*2];

// ---------------- helpers ----------------------------------------------------
__device__ __forceinline__ uint32_t smem_u32(const void* p) {
    uint32_t a;
    asm("{ .reg .u64 t; cvta.to.shared.u64 t, %1; cvt.u32.u64 %0, t; }" : "=r"(a) : "l"(p));
    return a;
}
__device__ __forceinline__ void cpa16(uint32_t dst, const void* src) {
    asm volatile("cp.async.cg.shared.global [%0], [%1], 16;" :: "r"(dst), "l"(src) : "memory");
}
__device__ __forceinline__ void cp_commit() {
    asm volatile("cp.async.commit_group;" ::: "memory");
}
__device__ __forceinline__ void mma_f16(float* c, const uint32_t* a, const uint32_t* b) {
    asm volatile(
        "mma.sync.aligned.m16n8k16.row.col.f32.f16.f16.f32 "
        "{%0,%1,%2,%3}, {%4,%5,%6,%7}, {%8,%9}, {%0,%1,%2,%3};"
        : "+f"(c[0]), "+f"(c[1]), "+f"(c[2]), "+f"(c[3])
        : "r"(a[0]), "r"(a[1]), "r"(a[2]), "r"(a[3]), "r"(b[0]), "r"(b[1]));
}
__device__ __forceinline__ uint32_t lds32h(const __half* p) {
    return *reinterpret_cast<const uint32_t*>(p);
}

// ---------------- small kernels ----------------------------------------------
__global__ void zero_cnt_kernel() {
    if (threadIdx.x < NE) g_cnt[threadIdx.x] = 0;
}

// f32 -> f16 elementwise
__global__ void cvt_kernel(const float* __restrict__ in, __half* __restrict__ out, int n4) {
    int i = blockIdx.x * blockDim.x + threadIdx.x;
    int stride = gridDim.x * blockDim.x;
    for (; i < n4; i += stride) {
        float4 v = reinterpret_cast<const float4*>(in)[i];
        __half2 lo = __floats2half2_rn(v.x, v.y);
        __half2 hi = __floats2half2_rn(v.z, v.w);
        uint2 pk = make_uint2(*reinterpret_cast<uint32_t*>(&lo),
                              *reinterpret_cast<uint32_t*>(&hi));
        reinterpret_cast<uint2*>(out)[i] = pk;
    }
}

// [R][C] f32 -> [C][R] f16, batched over z
__global__ void transcvt_kernel(const float* __restrict__ in, __half* __restrict__ out,
                                int R, int C) {
    __shared__ float tile[32][33];
    size_t boff = (size_t)blockIdx.z * R * C;
    const float* ib = in + boff;
    __half* ob = out + boff;
    int c0 = blockIdx.x * 32, r0 = blockIdx.y * 32;
    int tx = threadIdx.x, ty = threadIdx.y;
    #pragma unroll
    for (int i = 0; i < 4; i++)
        tile[ty + 8*i][tx] = ib[(size_t)(r0 + ty + 8*i) * C + c0 + tx];
    __syncthreads();
    #pragma unroll
    for (int i = 0; i < 4; i++)
        ob[(size_t)(c0 + ty + 8*i) * R + r0 + tx] = __float2half_rn(tile[tx][ty + 8*i]);
}

// ---------------- router ------------------------------------------------------
__global__ void router_kernel(const float* __restrict__ x,
                              const float* __restrict__ gw) {
    int gtid = blockIdx.x * blockDim.x + threadIdx.x;
    int t    = gtid >> 5;
    int lane = gtid & 31;
    if (t >= NT) return;
    const float* xr = x + (size_t)t * NH;

    float acc[8] = {0.f,0.f,0.f,0.f,0.f,0.f,0.f,0.f};
    for (int h = lane; h < NH; h += 32) {
        float xv = __ldg(xr + h);
        const float4* g4 = reinterpret_cast<const float4*>(gw + (size_t)h * 8);
        float4 a = __ldg(g4 + 0);
        float4 b = __ldg(g4 + 1);
        acc[0] = fmaf(xv, a.x, acc[0]); acc[1] = fmaf(xv, a.y, acc[1]);
        acc[2] = fmaf(xv, a.z, acc[2]); acc[3] = fmaf(xv, a.w, acc[3]);
        acc[4] = fmaf(xv, b.x, acc[4]); acc[5] = fmaf(xv, b.y, acc[5]);
        acc[6] = fmaf(xv, b.z, acc[6]); acc[7] = fmaf(xv, b.w, acc[7]);
    }
    #pragma unroll
    for (int e = 0; e < 8; e++)
        #pragma unroll
        for (int off = 16; off > 0; off >>= 1)
            acc[e] += __shfl_xor_sync(0xffffffffu, acc[e], off);
    if (lane == 0) {
        float m = acc[0];
        #pragma unroll
        for (int e = 1; e < 8; e++) m = fmaxf(m, acc[e]);
        float p[8], s = 0.f;
        #pragma unroll
        for (int e = 0; e < 8; e++) { p[e] = expf(acc[e] - m); s += p[e]; }
        float inv = 1.f / s;
        #pragma unroll
        for (int e = 0; e < 8; e++) p[e] *= inv;
        int i0 = 0; float v0 = p[0];
        #pragma unroll
        for (int e = 1; e < 8; e++) if (p[e] > v0) { v0 = p[e]; i0 = e; }
        int i1 = -1; float v1 = -1.f;
        #pragma unroll
        for (int e = 0; e < 8; e++) if (e != i0 && p[e] > v1) { v1 = p[e]; i1 = e; }
        float denom = v0 + v1 + 1e-6f;
        g_w[2*t]   = v0 / denom;
        g_w[2*t+1] = v1 / denom;
        int r0 = atomicAdd(&g_cnt[i0], 1);
        g_rowlist[i0*NT + r0] = t; g_pidlist[i0*NT + r0] = 2*t;
        int r1 = atomicAdd(&g_cnt[i1], 1);
        g_rowlist[i1*NT + r1] = t; g_pidlist[i1*NT + r1] = 2*t + 1;
    }
}

// ---------------- gate+up SwiGLU GEMM (fp16 mma) ------------------------------
// Block 128(M) x 128(N per matrix). 8 warps, warp tile 64x32 per matrix.
template<bool EXPERT>
__global__ __launch_bounds__(256, 1)
void gateup_mma(const __half* __restrict__ WgT,   // [*, NI, NH] k-contig
                const __half* __restrict__ WuT) {
    extern __shared__ __align__(16) char dsm[];
    __half* smh = reinterpret_cast<__half*>(dsm);
    const int e    = EXPERT ? blockIdx.z : 0;
    const int M    = EXPERT ? g_cnt[e] : NT;
    const int row0 = blockIdx.y * 128;
    if (row0 >= M) return;
    const int col0 = blockIdx.x * 128;

    const __half* wg = WgT + (EXPERT ? (size_t)e * NI * NH : (size_t)0);
    const __half* wu = WuT + (EXPERT ? (size_t)e * NI * NH : (size_t)0);
    __half* Hout = EXPERT ? (g_hbuf + (size_t)e * NT * NI) : g_shh;

    const int tid = threadIdx.x, wid = tid >> 5, lane = tid & 31;
    const uint32_t sbase = smem_u32(dsm);

    // copy roles: every source row is k-contiguous; k advances +KC per stage.
    const __half* s0; const __half* s1;
    uint32_t d0, d1;          // halfword offsets within stage
    if (tid < 128) {
        int r = tid;
        int li = row0 + r; if (li >= M) li = M - 1;
        int gr = EXPERT ? g_rowlist[e*NT + li] : li;
        s0 = s1 = g_xh + (size_t)gr * NH;
        d0 = d1 = (uint32_t)r * PADH;
    } else if (tid < 192) {
        int u = tid - 128;
        s0 = wg + (size_t)(col0 + u)      * NH;
        s1 = wg + (size_t)(col0 + u + 64) * NH;
        d0 = GU_BG_OFF + (uint32_t)u * PADH;
        d1 = GU_BG_OFF + (uint32_t)(u + 64) * PADH;
    } else {
        int u = tid - 192;
        s0 = wu + (size_t)(col0 + u)      * NH;
        s1 = wu + (size_t)(col0 + u + 64) * NH;
        d0 = GU_BU_OFF + (uint32_t)u * PADH;
        d1 = GU_BU_OFF + (uint32_t)(u + 64) * PADH;
    }
    const bool tworow = (tid >= 128);

    float accg[4][4][4], accu[4][4][4];
    #pragma unroll
    for (int i = 0; i < 4; i++)
        #pragma unroll
        for (int j = 0; j < 4; j++)
            #pragma unroll
            for (int q = 0; q < 4; q++) { accg[i][j][q] = 0.f; accu[i][j][q] = 0.f; }

    const int m0 = (wid & 1) * 64, n0 = (wid >> 1) * 32;
    const int tg = lane >> 2, ti = lane & 3;

    int koff = 0;
    #pragma unroll
    for (int s = 0; s < NSTAGE - 1; s++) {
        uint32_t base = sbase + (uint32_t)(s * GU_STAGE) * 2;
        #pragma unroll
        for (int c = 0; c < 8; c++) cpa16(base + (d0)*2 + c*16, s0 + koff + c*8);
        if (tworow) {
            #pragma unroll
            for (int c = 0; c < 8; c++) cpa16(base + (d1)*2 + c*16, s1 + koff + c*8);
        }
        cp_commit();
        koff += KC;
    }

    const int KST = NH / KC;   // 16
    for (int j = 0; j < KST; j++) {
        if (j < KST - 1) asm volatile("cp.async.wait_group 1;" ::: "memory");
        else             asm volatile("cp.async.wait_group 0;" ::: "memory");
        __syncthreads();
        if (j + NSTAGE - 1 < KST) {
            int s = (j + NSTAGE - 1) % NSTAGE;
            uint32_t base = sbase + (uint32_t)(s * GU_STAGE) * 2;
            #pragma unroll
            for (int c = 0; c < 8; c++) cpa16(base + (d0)*2 + c*16, s0 + koff + c*8);
            if (tworow) {
                #pragma unroll
                for (int c = 0; c < 8; c++) cpa16(base + (d1)*2 + c*16, s1 + koff + c*8);
            }
            cp_commit();
            koff += KC;
        }
        const __half* sA  = smh + (j % NSTAGE) * GU_STAGE;
        const __half* sBg = sA + GU_BG_OFF;
        const __half* sBu = sA + GU_BU_OFF;
        #pragma unroll
        for (int kk = 0; kk < 4; kk++) {
            const int k0 = kk * 16;
            uint32_t a[4][4];
            #pragma unroll
            for (int i = 0; i < 4; i++) {
                int r = m0 + i*16 + tg;
                a[i][0] = lds32h(sA + (size_t)r     * PADH + k0 + 2*ti);
                a[i][1] = lds32h(sA + (size_t)(r+8) * PADH + k0 + 2*ti);
                a[i][2] = lds32h(sA + (size_t)r     * PADH + k0 + 8 + 2*ti);
                a[i][3] = lds32h(sA + (size_t)(r+8) * PADH + k0 + 8 + 2*ti);
            }
            #pragma unroll
            for (int jn = 0; jn < 4; jn++) {
                int n = n0 + jn*8 + tg;
                uint32_t bg[2], bu[2];
                bg[0] = lds32h(sBg + (size_t)n * PADH + k0 + 2*ti);
                bg[1] = lds32h(sBg + (size_t)n * PADH + k0 + 8 + 2*ti);
                bu[0] = lds32h(sBu + (size_t)n * PADH + k0 + 2*ti);
                bu[1] = lds32h(sBu + (size_t)n * PADH + k0 + 8 + 2*ti);
                #pragma unroll
                for (int i = 0; i < 4; i++) {
                    mma_f16(accg[i][jn], a[i], bg);
                    mma_f16(accu[i][jn], a[i], bu);
                }
            }
        }
    }

    // epilogue: silu(g)*u -> fp16
    #pragma unroll
    for (int i = 0; i < 4; i++) {
        #pragma unroll
        for (int half_ = 0; half_ < 2; half_++) {
            int r = m0 + i*16 + half_*8 + tg;
            int lrow = row0 + r;
            if (lrow < M) {
                __half* hrow = Hout + (size_t)lrow * NI + col0 + n0;
                #pragma unroll
                for (int jn = 0; jn < 4; jn++) {
                    float g0 = accg[i][jn][half_*2+0], g1 = accg[i][jn][half_*2+1];
                    float u0 = accu[i][jn][half_*2+0], u1 = accu[i][jn][half_*2+1];
                    float h0 = g0 / (1.f + expf(-g0)) * u0;
                    float h1 = g1 / (1.f + expf(-g1)) * u1;
                    __half2 hv = __floats2half2_rn(h0, h1);
                    *reinterpret_cast<__half2*>(hrow + jn*8 + 2*ti) = hv;
                }
            }
        }
    }
}

// ---------------- down GEMM (fp16 mma) -----------------------------------------
// Block 128(M) x 256(N). 8 warps, warp tile 64x64.
template<bool EXPERT>
__global__ __launch_bounds__(256, 1)
void down_mma(const __half* __restrict__ WdT,    // [*, NH, NI] k-contig
              float* __restrict__ outp) {
    extern __shared__ __align__(16) char dsm[];
    __half* smh = reinterpret_cast<__half*>(dsm);
    const int e    = EXPERT ? blockIdx.z : 0;
    const int M    = EXPERT ? g_cnt[e] : NT;
    const int row0 = blockIdx.y * 128;
    if (row0 >= M) return;
    const int col0 = blockIdx.x * 256;

    const __half* A  = EXPERT ? (g_hbuf + (size_t)e * NT * NI) : g_shh;
    const __half* wd = WdT + (EXPERT ? (size_t)e * NH * NI : (size_t)0);

    const int tid = threadIdx.x, wid = tid >> 5, lane = tid & 31;
    const uint32_t sbase = smem_u32(dsm);

    const __half* s0; const __half* s1;
    uint32_t d0, d1;
    if (tid < 128) {
        int r = tid;
        int ar = row0 + r; if (ar >= M) ar = M - 1;
        s0 = s1 = A + (size_t)ar * NI;
        d0 = d1 = (uint32_t)r * PADH;
    } else {
        int u = tid - 128;
        s0 = wd + (size_t)(col0 + u)       * NI;
        s1 = wd + (size_t)(col0 + u + 128) * NI;
        d0 = DN_B_OFF + (uint32_t)u * PADH;
        d1 = DN_B_OFF + (uint32_t)(u + 128) * PADH;
    }
    const bool tworow = (tid >= 128);

    float acc[4][8][4];
    #pragma unroll
    for (int i = 0; i < 4; i++)
        #pragma unroll
        for (int j = 0; j < 8; j++)
            #pragma unroll
            for (int q = 0; q < 4; q++) acc[i][j][q] = 0.f;

    const int m0 = (wid & 1) * 64, n0 = (wid >> 1) * 64;
    const int tg = lane >> 2, ti = lane & 3;

    int koff = 0;
    #pragma unroll
    for (int s = 0; s < NSTAGE - 1; s++) {
        uint32_t base = sbase + (uint32_t)(s * DN_STAGE) * 2;
        #pragma unroll
        for (int c = 0; c < 8; c++) cpa16(base + (d0)*2 + c*16, s0 + koff + c*8);
        if (tworow) {
            #pragma unroll
            for (int c = 0; c < 8; c++) cpa16(base + (d1)*2 + c*16, s1 + koff + c*8);
        }
        cp_commit();
        koff += KC;
    }

    const int KST = NI / KC;   // 22
    for (int j = 0; j < KST; j++) {
        if (j < KST - 1) asm volatile("cp.async.wait_group 1;" ::: "memory");
        else             asm volatile("cp.async.wait_group 0;" ::: "memory");
        __syncthreads();
        if (j + NSTAGE - 1 < KST) {
            int s = (j + NSTAGE - 1) % NSTAGE;
            uint32_t base = sbase + (uint32_t)(s * DN_STAGE) * 2;
            #pragma unroll
            for (int c = 0; c < 8; c++) cpa16(base + (d0)*2 + c*16, s0 + koff + c*8);
            if (tworow) {
                #pragma unroll
                for (int c = 0; c < 8; c++) cpa16(base + (d1)*2 + c*16, s1 + koff + c*8);
            }
            cp_commit();
            koff += KC;
        }
        const __half* sA = smh + (j % NSTAGE) * DN_STAGE;
        const __half* sB = sA + DN_B_OFF;
        #pragma unroll
        for (int kk = 0; kk < 4; kk++) {
            const int k0 = kk * 16;
            uint32_t a[4][4];
            #pragma unroll
            for (int i = 0; i < 4; i++) {
                int r = m0 + i*16 + tg;
                a[i][0] = lds32h(sA + (size_t)r     * PADH + k0 + 2*ti);
                a[i][1] = lds32h(sA + (size_t)(r+8) * PADH + k0 + 2*ti);
                a[i][2] = lds32h(sA + (size_t)r     * PADH + k0 + 8 + 2*ti);
                a[i][3] = lds32h(sA + (size_t)(r+8) * PADH + k0 + 8 + 2*ti);
            }
            #pragma unroll
            for (int jn = 0; jn < 8; jn++) {
                int n = n0 + jn*8 + tg;
                uint32_t b[2];
                b[0] = lds32h(sB + (size_t)n * PADH + k0 + 2*ti);
                b[1] = lds32h(sB + (size_t)n * PADH + k0 + 8 + 2*ti);
                #pragma unroll
                for (int i = 0; i < 4; i++) mma_f16(acc[i][jn], a[i], b);
            }
        }
    }

    #pragma unroll
    for (int i = 0; i < 4; i++) {
        #pragma unroll
        for (int half_ = 0; half_ < 2; half_++) {
            int r = m0 + i*16 + half_*8 + tg;
            int lrow = row0 + r;
            if (lrow < M) {
                float* crow;
                if (EXPERT) crow = g_down + (size_t)g_pidlist[e*NT + lrow] * NH;
                else        crow = outp   + (size_t)lrow * NH;
                crow += col0 + n0;
                #pragma unroll
                for (int jn = 0; jn < 8; jn++) {
                    float2 v;
                    v.x = acc[i][jn][half_*2+0];
                    v.y = acc[i][jn][half_*2+1];
                    *reinterpret_cast<float2*>(crow + jn*8 + 2*ti) = v;
                }
            }
        }
    }
}

// ---------------- combine -------------------------------------------------------
__global__ void combine_kernel(float* __restrict__ outp) {
    int t = blockIdx.x;
    int i = threadIdx.x;
    float w0 = g_w[2*t], w1 = g_w[2*t+1];
    float4*       o = reinterpret_cast<float4*>(outp + (size_t)t * NH);
    const float4* a = reinterpret_cast<const float4*>(g_down + (size_t)(2*t)   * NH);
    const float4* b = reinterpret_cast<const float4*>(g_down + (size_t)(2*t+1) * NH);
    float4 ov = o[i], av = a[i], bv = b[i];
    ov.x = fmaf(w1, bv.x, fmaf(w0, av.x, ov.x));
    ov.y = fmaf(w1, bv.y, fmaf(w0, av.y, ov.y));
    ov.z = fmaf(w1, bv.z, fmaf(w0, av.z, ov.z));
    ov.w = fmaf(w1, bv.w, fmaf(w0, av.w, ov.w));
    o[i] = ov;
}

// ---------------- launch ----------------------------------------------------------
extern "C" void kernel_launch(void* const* d_in, const int* in_sizes, int n_in,
                              void* d_out, int out_size) {
    const float* x  = (const float*)d_in[0];
    const float* gw = (const float*)d_in[1];
    const float* eg = (const float*)d_in[2];
    const float* eu = (const float*)d_in[3];
    const float* ed = (const float*)d_in[4];
    const float* sg = (const float*)d_in[5];
    const float* su = (const float*)d_in[6];
    const float* sd = (const float*)d_in[7];
    float* out = (float*)d_out;

    static bool attr_done = false;
    if (!attr_done) {
        cudaFuncSetAttribute(gateup_mma<false>, cudaFuncAttributeMaxDynamicSharedMemorySize, GU_SMEM_BYTES);
        cudaFuncSetAttribute(gateup_mma<true>,  cudaFuncAttributeMaxDynamicSharedMemorySize, GU_SMEM_BYTES);
        cudaFuncSetAttribute(down_mma<false>,   cudaFuncAttributeMaxDynamicSharedMemorySize, DN_SMEM_BYTES);
        cudaFuncSetAttribute(down_mma<true>,    cudaFuncAttributeMaxDynamicSharedMemorySize, DN_SMEM_BYTES);
        attr_done = true;
    }

    __half *p_xh, *p_egT, *p_euT, *p_edT, *p_sgT, *p_suT, *p_sdT;
    cudaGetSymbolAddress((void**)&p_xh,  g_xh);
    cudaGetSymbolAddress((void**)&p_egT, g_egT);
    cudaGetSymbolAddress((void**)&p_euT, g_euT);
    cudaGetSymbolAddress((void**)&p_edT, g_edT);
    cudaGetSymbolAddress((void**)&p_sgT, g_sgT);
    cudaGetSymbolAddress((void**)&p_suT, g_suT);
    cudaGetSymbolAddress((void**)&p_sdT, g_sdT);

    zero_cnt_kernel<<<1, 32>>>();
    router_kernel<<<NT/4, 128>>>(x, gw);

    // fp16 conversion (+ transpose for weights: [K][N] -> [N][K])
    cvt_kernel<<<512, 256>>>(x, p_xh, NT*NH/4);
    dim3 tb(32, 8);
    transcvt_kernel<<<dim3(NI/32, NH/32, NE), tb>>>(eg, p_egT, NH, NI);
    transcvt_kernel<<<dim3(NI/32, NH/32, NE), tb>>>(eu, p_euT, NH, NI);
    transcvt_kernel<<<dim3(NH/32, NI/32, NE), tb>>>(ed, p_edT, NI, NH);
    transcvt_kernel<<<dim3(NI/32, NH/32, 1),  tb>>>(sg, p_sgT, NH, NI);
    transcvt_kernel<<<dim3(NI/32, NH/32, 1),  tb>>>(su, p_suT, NH, NI);
    transcvt_kernel<<<dim3(NH/32, NI/32, 1),  tb>>>(sd, p_sdT, NI, NH);

    // gate+up SwiGLU
    gateup_mma<false><<<dim3(NI/128, NT/128, 1),  256, GU_SMEM_BYTES>>>(p_sgT, p_suT);
    gateup_mma<true> <<<dim3(NI/128, NT/128, NE), 256, GU_SMEM_BYTES>>>(p_egT, p_euT);

    // down projection
    down_mma<false><<<dim3(NH/256, NT/128, 1),  256, DN_SMEM_BYTES>>>(p_sdT, out);
    down_mma<true> <<<dim3(NH/256, NT/128, NE), 256, DN_SMEM_BYTES>>>(p_edT, out);

    combine_kernel<<<NT, 256>>>(out);
}

// round 7
// speedup vs baseline: 4.1655x; 1.0589x over previous
#include <cuda_runtime.h>
#include <cuda_fp16.h>
#include <math.h>
#include <stdint.h>

// Problem dims (fixed)
#define NT 8192   // tokens
#define NH 1024   // hidden
#define NE 8      // experts
#define NI 1408   // intermediate

#define KC 64     // K halfs per pipeline stage
#define NSTAGE 3
#define PADH 72   // halfs per smem row (144B: ldmatrix row banks 0,16,..,112 -> conflict-free)

// gateup stage (halfs): A[128][72] + Bg[128][72] + Bu[128][72]
#define GU_BG_OFF (128 * PADH)
#define GU_BU_OFF (256 * PADH)
#define GU_STAGE  (384 * PADH)
#define GU_SMEM_BYTES (NSTAGE * GU_STAGE * 2)        // 165888

// down stage (halfs): A[128][72] + B[256][72]
#define DN_B_OFF  (128 * PADH)
#define DN_STAGE  (384 * PADH)
#define DN_SMEM_BYTES (NSTAGE * DN_STAGE * 2)        // 165888

// ---------------- scratch (device globals) ----------------------------------
__device__ __half g_xh [(size_t)NT*NH];
__device__ __half g_egT[(size_t)NE*NI*NH];       // fp16 weights, [N][K]
__device__ __half g_euT[(size_t)NE*NI*NH];
__device__ __half g_edT[(size_t)NE*NH*NI];
__device__ __half g_sgT[(size_t)NI*NH];
__device__ __half g_suT[(size_t)NI*NH];
__device__ __half g_sdT[(size_t)NH*NI];
__device__ __half g_hbuf[(size_t)NE*NT*NI];
__device__ __half g_shh [(size_t)NT*NI];
__device__ float  g_down[(size_t)2*NT*NH];
__device__ int    g_rowlist[NE*NT];
__device__ int    g_pidlist[NE*NT];
__device__ int    g_cnt[NE];
__device__ float  g_w[NT*2];

// ---------------- helpers ----------------------------------------------------
__device__ __forceinline__ uint32_t smem_u32(const void* p) {
    uint32_t a;
    asm("{ .reg .u64 t; cvta.to.shared.u64 t, %1; cvt.u32.u64 %0, t; }" : "=r"(a) : "l"(p));
    return a;
}
__device__ __forceinline__ void cpa16(uint32_t dst, const void* src) {
    asm volatile("cp.async.cg.shared.global [%0], [%1], 16;" :: "r"(dst), "l"(src) : "memory");
}
__device__ __forceinline__ void cp_commit() {
    asm volatile("cp.async.commit_group;" ::: "memory");
}
__device__ __forceinline__ void mma_f16(float* c, const uint32_t* a, const uint32_t* b) {
    asm volatile(
        "mma.sync.aligned.m16n8k16.row.col.f32.f16.f16.f32 "
        "{%0,%1,%2,%3}, {%4,%5,%6,%7}, {%8,%9}, {%0,%1,%2,%3};"
        : "+f"(c[0]), "+f"(c[1]), "+f"(c[2]), "+f"(c[3])
        : "r"(a[0]), "r"(a[1]), "r"(a[2]), "r"(a[3]), "r"(b[0]), "r"(b[1]));
}
__device__ __forceinline__ void ldsm4(uint32_t addr, uint32_t& r0, uint32_t& r1,
                                      uint32_t& r2, uint32_t& r3) {
    asm volatile("ldmatrix.sync.aligned.m8n8.x4.shared.b16 {%0,%1,%2,%3}, [%4];"
                 : "=r"(r0), "=r"(r1), "=r"(r2), "=r"(r3) : "r"(addr));
}

// ---------------- small kernels ----------------------------------------------
__global__ void zero_cnt_kernel() {
    if (threadIdx.x < NE) g_cnt[threadIdx.x] = 0;
}

__global__ void cvt_kernel(const float* __restrict__ in, __half* __restrict__ out, int n4) {
    int i = blockIdx.x * blockDim.x + threadIdx.x;
    int stride = gridDim.x * blockDim.x;
    for (; i < n4; i += stride) {
        float4 v = reinterpret_cast<const float4*>(in)[i];
        __half2 lo = __floats2half2_rn(v.x, v.y);
        __half2 hi = __floats2half2_rn(v.z, v.w);
        uint2 pk = make_uint2(*reinterpret_cast<uint32_t*>(&lo),
                              *reinterpret_cast<uint32_t*>(&hi));
        reinterpret_cast<uint2*>(out)[i] = pk;
    }
}

// [R][C] f32 -> [C][R] f16; 64(R) x 32(C) tiles, half2 stores (128B transactions)
__global__ void transcvt_kernel(const float* __restrict__ in, __half* __restrict__ out,
                                int R, int C) {
    __shared__ float tile[32][65];   // [c][r]
    size_t boff = (size_t)blockIdx.z * R * C;
    const float* ib = in + boff;
    __half* ob = out + boff;
    int c0 = blockIdx.x * 32, r0 = blockIdx.y * 64;
    int tx = threadIdx.x, ty = threadIdx.y;
    #pragma unroll
    for (int i = 0; i < 8; i++) {
        int r = ty + 8*i;
        tile[tx][r] = ib[(size_t)(r0 + r) * C + c0 + tx];
    }
    __syncthreads();
    #pragma unroll
    for (int ic = 0; ic < 4; ic++) {
        int c = ty + 8*ic;
        __half2 v = __floats2half2_rn(tile[c][2*tx], tile[c][2*tx+1]);
        *reinterpret_cast<__half2*>(ob + (size_t)(c0 + c) * R + r0 + 2*tx) = v;
    }
}

// ---------------- router ------------------------------------------------------
__global__ void router_kernel(const float* __restrict__ x,
                              const float* __restrict__ gw) {
    int gtid = blockIdx.x * blockDim.x + threadIdx.x;
    int t    = gtid >> 5;
    int lane = gtid & 31;
    if (t >= NT) return;
    const float* xr = x + (size_t)t * NH;

    float acc[8] = {0.f,0.f,0.f,0.f,0.f,0.f,0.f,0.f};
    for (int h = lane; h < NH; h += 32) {
        float xv = __ldg(xr + h);
        const float4* g4 = reinterpret_cast<const float4*>(gw + (size_t)h * 8);
        float4 a = __ldg(g4 + 0);
        float4 b = __ldg(g4 + 1);
        acc[0] = fmaf(xv, a.x, acc[0]); acc[1] = fmaf(xv, a.y, acc[1]);
        acc[2] = fmaf(xv, a.z, acc[2]); acc[3] = fmaf(xv, a.w, acc[3]);
        acc[4] = fmaf(xv, b.x, acc[4]); acc[5] = fmaf(xv, b.y, acc[5]);
        acc[6] = fmaf(xv, b.z, acc[6]); acc[7] = fmaf(xv, b.w, acc[7]);
    }
    #pragma unroll
    for (int e = 0; e < 8; e++)
        #pragma unroll
        for (int off = 16; off > 0; off >>= 1)
            acc[e] += __shfl_xor_sync(0xffffffffu, acc[e], off);
    if (lane == 0) {
        float m = acc[0];
        #pragma unroll
        for (int e = 1; e < 8; e++) m = fmaxf(m, acc[e]);
        float p[8], s = 0.f;
        #pragma unroll
        for (int e = 0; e < 8; e++) { p[e] = expf(acc[e] - m); s += p[e]; }
        float inv = 1.f / s;
        #pragma unroll
        for (int e = 0; e < 8; e++) p[e] *= inv;
        int i0 = 0; float v0 = p[0];
        #pragma unroll
        for (int e = 1; e < 8; e++) if (p[e] > v0) { v0 = p[e]; i0 = e; }
        int i1 = -1; float v1 = -1.f;
        #pragma unroll
        for (int e = 0; e < 8; e++) if (e != i0 && p[e] > v1) { v1 = p[e]; i1 = e; }
        float denom = v0 + v1 + 1e-6f;
        g_w[2*t]   = v0 / denom;
        g_w[2*t+1] = v1 / denom;
        int r0 = atomicAdd(&g_cnt[i0], 1);
        g_rowlist[i0*NT + r0] = t; g_pidlist[i0*NT + r0] = 2*t;
        int r1 = atomicAdd(&g_cnt[i1], 1);
        g_rowlist[i1*NT + r1] = t; g_pidlist[i1*NT + r1] = 2*t + 1;
    }
}

// ---------------- gate+up SwiGLU GEMM (fp16 mma + ldmatrix) --------------------
// Block 128(M) x 128(N per matrix). 8 warps, warp tile 64x32 per matrix.
template<bool EXPERT>
__global__ __launch_bounds__(256, 1)
void gateup_mma(const __half* __restrict__ WgT,   // [*, NI, NH] k-contig
                const __half* __restrict__ WuT) {
    extern __shared__ __align__(16) char dsm[];
    __half* smh = reinterpret_cast<__half*>(dsm);
    const int e    = EXPERT ? blockIdx.z : 0;
    const int M    = EXPERT ? g_cnt[e] : NT;
    const int row0 = blockIdx.y * 128;
    if (row0 >= M) return;
    const int col0 = blockIdx.x * 128;

    const __half* wg = WgT + (EXPERT ? (size_t)e * NI * NH : (size_t)0);
    const __half* wu = WuT + (EXPERT ? (size_t)e * NI * NH : (size_t)0);
    __half* Hout = EXPERT ? (g_hbuf + (size_t)e * NT * NI) : g_shh;

    const int tid = threadIdx.x, wid = tid >> 5, lane = tid & 31;
    const uint32_t sbase = smem_u32(dsm);

    // copy roles
    const __half* s0; const __half* s1;
    uint32_t d0, d1;
    if (tid < 128) {
        int r = tid;
        int li = row0 + r; if (li >= M) li = M - 1;
        int gr = EXPERT ? g_rowlist[e*NT + li] : li;
        s0 = s1 = g_xh + (size_t)gr * NH;
        d0 = d1 = (uint32_t)r * PADH;
    } else if (tid < 192) {
        int u = tid - 128;
        s0 = wg + (size_t)(col0 + u)      * NH;
        s1 = wg + (size_t)(col0 + u + 64) * NH;
        d0 = GU_BG_OFF + (uint32_t)u * PADH;
        d1 = GU_BG_OFF + (uint32_t)(u + 64) * PADH;
    } else {
        int u = tid - 192;
        s0 = wu + (size_t)(col0 + u)      * NH;
        s1 = wu + (size_t)(col0 + u + 64) * NH;
        d0 = GU_BU_OFF + (uint32_t)u * PADH;
        d1 = GU_BU_OFF + (uint32_t)(u + 64) * PADH;
    }
    const bool tworow = (tid >= 128);

    float accg[4][4][4], accu[4][4][4];
    #pragma unroll
    for (int i = 0; i < 4; i++)
        #pragma unroll
        for (int j = 0; j < 4; j++)
            #pragma unroll
            for (int q = 0; q < 4; q++) { accg[i][j][q] = 0.f; accu[i][j][q] = 0.f; }

    const int m0 = (wid & 1) * 64, n0 = (wid >> 1) * 32;
    const int tg = lane >> 2, ti = lane & 3;

    // ldmatrix per-lane byte offsets within a stage
    const int q8 = lane >> 3, l7 = lane & 7;
    const uint32_t aoff  = (uint32_t)((m0 + (q8 & 1)*8 + l7) * PADH + (q8 >> 1)*8) * 2;
    const uint32_t bgoff = (uint32_t)(GU_BG_OFF + (n0 + (q8 >> 1)*8 + l7) * PADH + (q8 & 1)*8) * 2;
    const uint32_t buoff = (uint32_t)(GU_BU_OFF + (n0 + (q8 >> 1)*8 + l7) * PADH + (q8 & 1)*8) * 2;

    int koff = 0;
    #pragma unroll
    for (int s = 0; s < NSTAGE - 1; s++) {
        uint32_t base = sbase + (uint32_t)(s * GU_STAGE) * 2;
        #pragma unroll
        for (int c = 0; c < 8; c++) cpa16(base + d0*2 + c*16, s0 + koff + c*8);
        if (tworow) {
            #pragma unroll
            for (int c = 0; c < 8; c++) cpa16(base + d1*2 + c*16, s1 + koff + c*8);
        }
        cp_commit();
        koff += KC;
    }

    const int KST = NH / KC;   // 16
    for (int j = 0; j < KST; j++) {
        if (j < KST - 1) asm volatile("cp.async.wait_group 1;" ::: "memory");
        else             asm volatile("cp.async.wait_group 0;" ::: "memory");
        __syncthreads();
        if (j + NSTAGE - 1 < KST) {
            int s = (j + NSTAGE - 1) % NSTAGE;
            uint32_t base = sbase + (uint32_t)(s * GU_STAGE) * 2;
            #pragma unroll
            for (int c = 0; c < 8; c++) cpa16(base + d0*2 + c*16, s0 + koff + c*8);
            if (tworow) {
                #pragma unroll
                for (int c = 0; c < 8; c++) cpa16(base + d1*2 + c*16, s1 + koff + c*8);
            }
            cp_commit();
            koff += KC;
        }
        const uint32_t stg = sbase + (uint32_t)((j % NSTAGE) * GU_STAGE) * 2;
        #pragma unroll
        for (int kk = 0; kk < 4; kk++) {
            const uint32_t kb = (uint32_t)(kk * 16) * 2;
            uint32_t a[4][4];
            #pragma unroll
            for (int i = 0; i < 4; i++)
                ldsm4(stg + aoff + (uint32_t)(i*16*PADH)*2 + kb,
                      a[i][0], a[i][1], a[i][2], a[i][3]);
            uint32_t bg[4][2], bu[4][2];
            #pragma unroll
            for (int jp = 0; jp < 2; jp++) {
                ldsm4(stg + bgoff + (uint32_t)(jp*16*PADH)*2 + kb,
                      bg[2*jp][0], bg[2*jp][1], bg[2*jp+1][0], bg[2*jp+1][1]);
                ldsm4(stg + buoff + (uint32_t)(jp*16*PADH)*2 + kb,
                      bu[2*jp][0], bu[2*jp][1], bu[2*jp+1][0], bu[2*jp+1][1]);
            }
            #pragma unroll
            for (int jn = 0; jn < 4; jn++)
                #pragma unroll
                for (int i = 0; i < 4; i++) {
                    mma_f16(accg[i][jn], a[i], bg[jn]);
                    mma_f16(accu[i][jn], a[i], bu[jn]);
                }
        }
    }

    // epilogue: silu(g)*u -> fp16
    #pragma unroll
    for (int i = 0; i < 4; i++) {
        #pragma unroll
        for (int half_ = 0; half_ < 2; half_++) {
            int r = m0 + i*16 + half_*8 + tg;
            int lrow = row0 + r;
            if (lrow < M) {
                __half* hrow = Hout + (size_t)lrow * NI + col0 + n0;
                #pragma unroll
                for (int jn = 0; jn < 4; jn++) {
                    float g0 = accg[i][jn][half_*2+0], g1 = accg[i][jn][half_*2+1];
                    float u0 = accu[i][jn][half_*2+0], u1 = accu[i][jn][half_*2+1];
                    float h0 = g0 / (1.f + expf(-g0)) * u0;
                    float h1 = g1 / (1.f + expf(-g1)) * u1;
                    __half2 hv = __floats2half2_rn(h0, h1);
                    *reinterpret_cast<__half2*>(hrow + jn*8 + 2*ti) = hv;
                }
            }
        }
    }
}

// ---------------- down GEMM (fp16 mma + ldmatrix) ------------------------------
// Block 128(M) x 256(N). 8 warps, warp tile 64x64.
template<bool EXPERT>
__global__ __launch_bounds__(256, 1)
void down_mma(const __half* __restrict__ WdT,    // [*, NH, NI] k-contig
              float* __restrict__ outp) {
    extern __shared__ __align__(16) char dsm[];
    const int e    = EXPERT ? blockIdx.z : 0;
    const int M    = EXPERT ? g_cnt[e] : NT;
    const int row0 = blockIdx.y * 128;
    if (row0 >= M) return;
    const int col0 = blockIdx.x * 256;

    const __half* A  = EXPERT ? (g_hbuf + (size_t)e * NT * NI) : g_shh;
    const __half* wd = WdT + (EXPERT ? (size_t)e * NH * NI : (size_t)0);

    const int tid = threadIdx.x, wid = tid >> 5, lane = tid & 31;
    const uint32_t sbase = smem_u32(dsm);

    const __half* s0; const __half* s1;
    uint32_t d0, d1;
    if (tid < 128) {
        int r = tid;
        int ar = row0 + r; if (ar >= M) ar = M - 1;
        s0 = s1 = A + (size_t)ar * NI;
        d0 = d1 = (uint32_t)r * PADH;
    } else {
        int u = tid - 128;
        s0 = wd + (size_t)(col0 + u)       * NI;
        s1 = wd + (size_t)(col0 + u + 128) * NI;
        d0 = DN_B_OFF + (uint32_t)u * PADH;
        d1 = DN_B_OFF + (uint32_t)(u + 128) * PADH;
    }
    const bool tworow = (tid >= 128);

    float acc[4][8][4];
    #pragma unroll
    for (int i = 0; i < 4; i++)
        #pragma unroll
        for (int j = 0; j < 8; j++)
            #pragma unroll
            for (int q = 0; q < 4; q++) acc[i][j][q] = 0.f;

    const int m0 = (wid & 1) * 64, n0 = (wid >> 1) * 64;
    const int tg = lane >> 2, ti = lane & 3;

    const int q8 = lane >> 3, l7 = lane & 7;
    const uint32_t aoff = (uint32_t)((m0 + (q8 & 1)*8 + l7) * PADH + (q8 >> 1)*8) * 2;
    const uint32_t boff = (uint32_t)(DN_B_OFF + (n0 + (q8 >> 1)*8 + l7) * PADH + (q8 & 1)*8) * 2;

    int koff = 0;
    #pragma unroll
    for (int s = 0; s < NSTAGE - 1; s++) {
        uint32_t base = sbase + (uint32_t)(s * DN_STAGE) * 2;
        #pragma unroll
        for (int c = 0; c < 8; c++) cpa16(base + d0*2 + c*16, s0 + koff + c*8);
        if (tworow) {
            #pragma unroll
            for (int c = 0; c < 8; c++) cpa16(base + d1*2 + c*16, s1 + koff + c*8);
        }
        cp_commit();
        koff += KC;
    }

    const int KST = NI / KC;   // 22
    for (int j = 0; j < KST; j++) {
        if (j < KST - 1) asm volatile("cp.async.wait_group 1;" ::: "memory");
        else             asm volatile("cp.async.wait_group 0;" ::: "memory");
        __syncthreads();
        if (j + NSTAGE - 1 < KST) {
            int s = (j + NSTAGE - 1) % NSTAGE;
            uint32_t base = sbase + (uint32_t)(s * DN_STAGE) * 2;
            #pragma unroll
            for (int c = 0; c < 8; c++) cpa16(base + d0*2 + c*16, s0 + koff + c*8);
            if (tworow) {
                #pragma unroll
                for (int c = 0; c < 8; c++) cpa16(base + d1*2 + c*16, s1 + koff + c*8);
            }
            cp_commit();
            koff += KC;
        }
        const uint32_t stg = sbase + (uint32_t)((j % NSTAGE) * DN_STAGE) * 2;
        #pragma unroll
        for (int kk = 0; kk < 4; kk++) {
            const uint32_t kb = (uint32_t)(kk * 16) * 2;
            uint32_t a[4][4];
            #pragma unroll
            for (int i = 0; i < 4; i++)
                ldsm4(stg + aoff + (uint32_t)(i*16*PADH)*2 + kb,
                      a[i][0], a[i][1], a[i][2], a[i][3]);
            uint32_t b[8][2];
            #pragma unroll
            for (int jp = 0; jp < 4; jp++)
                ldsm4(stg + boff + (uint32_t)(jp*16*PADH)*2 + kb,
                      b[2*jp][0], b[2*jp][1], b[2*jp+1][0], b[2*jp+1][1]);
            #pragma unroll
            for (int jn = 0; jn < 8; jn++)
                #pragma unroll
                for (int i = 0; i < 4; i++)
                    mma_f16(acc[i][jn], a[i], b[jn]);
        }
    }

    #pragma unroll
    for (int i = 0; i < 4; i++) {
        #pragma unroll
        for (int half_ = 0; half_ < 2; half_++) {
            int r = m0 + i*16 + half_*8 + tg;
            int lrow = row0 + r;
            if (lrow < M) {
                float* crow;
                if (EXPERT) crow = g_down + (size_t)g_pidlist[e*NT + lrow] * NH;
                else        crow = outp   + (size_t)lrow * NH;
                crow += col0 + n0;
                #pragma unroll
                for (int jn = 0; jn < 8; jn++) {
                    float2 v;
                    v.x = acc[i][jn][half_*2+0];
                    v.y = acc[i][jn][half_*2+1];
                    *reinterpret_cast<float2*>(crow + jn*8 + 2*ti) = v;
                }
            }
        }
    }
}

// ---------------- combine -------------------------------------------------------
__global__ void combine_kernel(float* __restrict__ outp) {
    int t = blockIdx.x;
    int i = threadIdx.x;
    float w0 = g_w[2*t], w1 = g_w[2*t+1];
    float4*       o = reinterpret_cast<float4*>(outp + (size_t)t * NH);
    const float4* a = reinterpret_cast<const float4*>(g_down + (size_t)(2*t)   * NH);
    const float4* b = reinterpret_cast<const float4*>(g_down + (size_t)(2*t+1) * NH);
    float4 ov = o[i], av = a[i], bv = b[i];
    ov.x = fmaf(w1, bv.x, fmaf(w0, av.x, ov.x));
    ov.y = fmaf(w1, bv.y, fmaf(w0, av.y, ov.y));
    ov.z = fmaf(w1, bv.z, fmaf(w0, av.z, ov.z));
    ov.w = fmaf(w1, bv.w, fmaf(w0, av.w, ov.w));
    o[i] = ov;
}

// ---------------- launch ----------------------------------------------------------
extern "C" void kernel_launch(void* const* d_in, const int* in_sizes, int n_in,
                              void* d_out, int out_size) {
    const float* x  = (const float*)d_in[0];
    const float* gw = (const float*)d_in[1];
    const float* eg = (const float*)d_in[2];
    const float* eu = (const float*)d_in[3];
    const float* ed = (const float*)d_in[4];
    const float* sg = (const float*)d_in[5];
    const float* su = (const float*)d_in[6];
    const float* sd = (const float*)d_in[7];
    float* out = (float*)d_out;

    static bool attr_done = false;
    if (!attr_done) {
        cudaFuncSetAttribute(gateup_mma<false>, cudaFuncAttributeMaxDynamicSharedMemorySize, GU_SMEM_BYTES);
        cudaFuncSetAttribute(gateup_mma<true>,  cudaFuncAttributeMaxDynamicSharedMemorySize, GU_SMEM_BYTES);
        cudaFuncSetAttribute(down_mma<false>,   cudaFuncAttributeMaxDynamicSharedMemorySize, DN_SMEM_BYTES);
        cudaFuncSetAttribute(down_mma<true>,    cudaFuncAttributeMaxDynamicSharedMemorySize, DN_SMEM_BYTES);
        attr_done = true;
    }

    __half *p_xh, *p_egT, *p_euT, *p_edT, *p_sgT, *p_suT, *p_sdT;
    cudaGetSymbolAddress((void**)&p_xh,  g_xh);
    cudaGetSymbolAddress((void**)&p_egT, g_egT);
    cudaGetSymbolAddress((void**)&p_euT, g_euT);
    cudaGetSymbolAddress((void**)&p_edT, g_edT);
    cudaGetSymbolAddress((void**)&p_sgT, g_sgT);
    cudaGetSymbolAddress((void**)&p_suT, g_suT);
    cudaGetSymbolAddress((void**)&p_sdT, g_sdT);

    zero_cnt_kernel<<<1, 32>>>();
    router_kernel<<<NT/4, 128>>>(x, gw);

    // fp16 conversion (+ transpose for weights: [K][N] -> [N][K])
    cvt_kernel<<<512, 256>>>(x, p_xh, NT*NH/4);
    dim3 tb(32, 8);
    transcvt_kernel<<<dim3(NI/32, NH/64, NE), tb>>>(eg, p_egT, NH, NI);
    transcvt_kernel<<<dim3(NI/32, NH/64, NE), tb>>>(eu, p_euT, NH, NI);
    transcvt_kernel<<<dim3(NH/32, NI/64, NE), tb>>>(ed, p_edT, NI, NH);
    transcvt_kernel<<<dim3(NI/32, NH/64, 1),  tb>>>(sg, p_sgT, NH, NI);
    transcvt_kernel<<<dim3(NI/32, NH/64, 1),  tb>>>(su, p_suT, NH, NI);
    transcvt_kernel<<<dim3(NH/32, NI/64, 1),  tb>>>(sd, p_sdT, NI, NH);

    // gate+up SwiGLU
    gateup_mma<false><<<dim3(NI/128, NT/128, 1),  256, GU_SMEM_BYTES>>>(p_sgT, p_suT);
    gateup_mma<true> <<<dim3(NI/128, NT/128, NE), 256, GU_SMEM_BYTES>>>(p_egT, p_euT);

    // down projection
    down_mma<false><<<dim3(NH/256, NT/128, 1),  256, DN_SMEM_BYTES>>>(p_sdT, out);
    down_mma<true> <<<dim3(NH/256, NT/128, NE), 256, DN_SMEM_BYTES>>>(p_edT, out);

    combine_kernel<<<NT, 256>>>(out);
}